// round 5
// baseline (speedup 1.0000x reference)
#include <cuda_runtime.h>
#include <math.h>

#define NN 100000
#define NE 1600000
#define DH 128
#define NC 64

// ---------------- scratch (static device allocations; no cudaMalloc) ----------------
__device__ int   g_deg[NN];
__device__ int   g_fill[NN];
__device__ int   g_rowptr[NN + 1];
__device__ float g_invdeg[NN];
__device__ int   g_adj[NE];
__device__ float g_x [(size_t)NN * DH];
__device__ float g_h1[(size_t)NN * DH];
__device__ float g_h2[(size_t)NN * DH];

// ---------------- CSR build ----------------
__global__ void k_zero(int n) {
    int i = blockIdx.x * blockDim.x + threadIdx.x;
    if (i < n) { g_deg[i] = 0; g_fill[i] = 0; }
}

__global__ void k_hist(const int* __restrict__ dst, int E) {
    int i = blockIdx.x * blockDim.x + threadIdx.x;
    if (i < E) atomicAdd(&g_deg[dst[i]], 1);
}

// Single-block exclusive scan over degrees -> rowptr, plus inv_deg.
__global__ void k_scan(int n) {
    __shared__ int sums[1024];
    int tid = threadIdx.x;
    int per = (n + 1023) / 1024;
    int b = tid * per;
    int e = min(b + per, n);
    int s = 0;
    for (int i = b; i < e; i++) s += g_deg[i];
    sums[tid] = s;
    __syncthreads();
    for (int off = 1; off < 1024; off <<= 1) {
        int v = (tid >= off) ? sums[tid - off] : 0;
        __syncthreads();
        sums[tid] += v;
        __syncthreads();
    }
    int run = sums[tid] - s;  // exclusive prefix
    for (int i = b; i < e; i++) {
        g_rowptr[i] = run;
        int d = g_deg[i];
        g_invdeg[i] = 1.0f / fmaxf((float)d, 1.0f);
        run += d;
    }
    if (tid == 1023) g_rowptr[n] = sums[1023];
}

__global__ void k_fill(const int* __restrict__ src, const int* __restrict__ dst, int E) {
    int i = blockIdx.x * blockDim.x + threadIdx.x;
    if (i < E) {
        int d = dst[i];
        int p = atomicAdd(&g_fill[d], 1);
        g_adj[g_rowptr[d] + p] = src[i];
    }
}

// ---------------- mean aggregation: 1 warp per node, atomic-free ----------------
__global__ void k_agg(const float* __restrict__ feat, float* __restrict__ out, int n) {
    int node = blockIdx.x * (blockDim.x >> 5) + (threadIdx.x >> 5);
    if (node >= n) return;
    int lane = threadIdx.x & 31;
    int s = g_rowptr[node];
    int e = g_rowptr[node + 1];
    float4 acc = make_float4(0.f, 0.f, 0.f, 0.f);
    const float4* f4 = (const float4*)feat;
    for (int i = s; i < e; i++) {
        int sn = g_adj[i];
        float4 v = f4[(size_t)sn * 32 + lane];
        acc.x += v.x; acc.y += v.y; acc.z += v.z; acc.w += v.w;
    }
    float sc = g_invdeg[node];
    acc.x *= sc; acc.y *= sc; acc.z *= sc; acc.w *= sc;
    ((float4*)out)[(size_t)node * 32 + lane] = acc;
}

// ---------------- GEMM  out = relu(A[M,128] @ W[128,128]^T + b) ----------------
// Block: 256 threads, 64 rows. Thread (tx,ty): cols {tx,tx+32,tx+64,tx+96},
// rows {i*8+ty}. Ws padded to stride 129 (conflict-free loads & stores).
__global__ void k_gemm_relu(const float* __restrict__ A, const float* __restrict__ W,
                            const float* __restrict__ bias, float* __restrict__ out, int M) {
    extern __shared__ float sm[];
    float* Ws = sm;                 // 128 * 129
    float* As = sm + 128 * 129;     // 64 * 128
    int tid = threadIdx.x;

    for (int idx = tid; idx < 128 * 128; idx += 256) {
        int j = idx >> 7, k = idx & 127;      // coalesced global read W[j][k]
        Ws[k * 129 + j] = W[idx];             // stride-129: conflict-free store
    }
    int row0 = blockIdx.x * 64;
    for (int idx = tid; idx < 64 * 32; idx += 256) {
        int r = idx >> 5, c = idx & 31;
        int row = row0 + r;
        float4 v = make_float4(0.f, 0.f, 0.f, 0.f);
        if (row < M) v = ((const float4*)A)[(size_t)row * 32 + c];
        ((float4*)As)[idx] = v;
    }
    __syncthreads();

    int tx = tid & 31, ty = tid >> 5;
    float acc[8][4];
#pragma unroll
    for (int i = 0; i < 8; i++)
#pragma unroll
        for (int c = 0; c < 4; c++) acc[i][c] = 0.f;

#pragma unroll 4
    for (int k = 0; k < 128; k++) {
        const float* wrow = Ws + k * 129;
        float b0 = wrow[tx], b1 = wrow[tx + 32], b2 = wrow[tx + 64], b3 = wrow[tx + 96];
#pragma unroll
        for (int i = 0; i < 8; i++) {
            float a = As[(i * 8 + ty) * 128 + k];   // warp-broadcast
            acc[i][0] += a * b0;
            acc[i][1] += a * b1;
            acc[i][2] += a * b2;
            acc[i][3] += a * b3;
        }
    }
    float bb0 = bias[tx], bb1 = bias[tx + 32], bb2 = bias[tx + 64], bb3 = bias[tx + 96];
#pragma unroll
    for (int i = 0; i < 8; i++) {
        int row = row0 + i * 8 + ty;
        if (row < M) {
            float* o = out + (size_t)row * 128;
            o[tx]      = fmaxf(acc[i][0] + bb0, 0.f);
            o[tx + 32] = fmaxf(acc[i][1] + bb1, 0.f);
            o[tx + 64] = fmaxf(acc[i][2] + bb2, 0.f);
            o[tx + 96] = fmaxf(acc[i][3] + bb3, 0.f);
        }
    }
}

// ---------------- final: logits = [h1|h2] @ Wl^T + bl, then log_softmax ----------------
// K=256 (h1 then h2), N=64. Each row's 64 logits live in one warp (2 per lane).
__global__ void k_final(const float* __restrict__ h1, const float* __restrict__ h2,
                        const float* __restrict__ W, const float* __restrict__ bias,
                        float* __restrict__ out, int M) {
    extern __shared__ float sm[];
    float* Ws = sm;                 // 256 * 65
    float* As = sm + 256 * 65;      // 64 * 256
    int tid = threadIdx.x;

    for (int idx = tid; idx < 64 * 256; idx += 256) {
        int j = idx >> 8, k = idx & 255;
        Ws[k * 65 + j] = W[idx];
    }
    int row0 = blockIdx.x * 64;
    for (int idx = tid; idx < 64 * 64; idx += 256) {
        int r = idx >> 6, c = idx & 63;       // float4 units over 256 floats
        int row = row0 + r;
        float4 v = make_float4(0.f, 0.f, 0.f, 0.f);
        if (row < M) {
            if (c < 32) v = ((const float4*)h1)[(size_t)row * 32 + c];
            else        v = ((const float4*)h2)[(size_t)row * 32 + (c - 32)];
        }
        ((float4*)As)[r * 64 + c] = v;
    }
    __syncthreads();

    int tx = tid & 31, ty = tid >> 5;
    float acc[8][2];
#pragma unroll
    for (int i = 0; i < 8; i++) { acc[i][0] = 0.f; acc[i][1] = 0.f; }

#pragma unroll 4
    for (int k = 0; k < 256; k++) {
        const float* wrow = Ws + k * 65;
        float b0 = wrow[tx], b1 = wrow[tx + 32];
#pragma unroll
        for (int i = 0; i < 8; i++) {
            float a = As[(i * 8 + ty) * 256 + k];
            acc[i][0] += a * b0;
            acc[i][1] += a * b1;
        }
    }
    float bb0 = bias[tx], bb1 = bias[tx + 32];
#pragma unroll
    for (int i = 0; i < 8; i++) {
        int row = row0 + i * 8 + ty;
        float l0 = acc[i][0] + bb0;
        float l1 = acc[i][1] + bb1;
        float m = fmaxf(l0, l1);
#pragma unroll
        for (int off = 16; off; off >>= 1)
            m = fmaxf(m, __shfl_xor_sync(0xffffffffu, m, off));
        float ssum = expf(l0 - m) + expf(l1 - m);
#pragma unroll
        for (int off = 16; off; off >>= 1)
            ssum += __shfl_xor_sync(0xffffffffu, ssum, off);
        float ls = m + logf(ssum);
        if (row < M) {
            out[(size_t)row * 64 + tx]      = l0 - ls;
            out[(size_t)row * 64 + tx + 32] = l1 - ls;
        }
    }
}

// ---------------- launch ----------------
extern "C" void kernel_launch(void* const* d_in, const int* in_sizes, int n_in,
                              void* d_out, int out_size) {
    const float* feat = (const float*)d_in[0];
    const int*   src  = (const int*)d_in[1];
    const int*   dst  = (const int*)d_in[2];
    const float* W1   = (const float*)d_in[3];
    const float* b1   = (const float*)d_in[4];
    const float* W2   = (const float*)d_in[5];
    const float* b2   = (const float*)d_in[6];
    const float* Wl   = (const float*)d_in[7];
    const float* bl   = (const float*)d_in[8];
    float* out = (float*)d_out;

    int n = in_sizes[0] / DH;
    int E = in_sizes[1];

    void *px, *ph1, *ph2;
    cudaGetSymbolAddress(&px,  g_x);
    cudaGetSymbolAddress(&ph1, g_h1);
    cudaGetSymbolAddress(&ph2, g_h2);

    const int SMEM_GEMM  = (128 * 129 + 64 * 128) * 4;   //  98816 B
    const int SMEM_FINAL = (256 * 65 + 64 * 256) * 4;    // 132096 B
    cudaFuncSetAttribute(k_gemm_relu, cudaFuncAttributeMaxDynamicSharedMemorySize, SMEM_GEMM);
    cudaFuncSetAttribute(k_final,     cudaFuncAttributeMaxDynamicSharedMemorySize, SMEM_FINAL);

    // CSR build
    k_zero<<<(n + 255) / 256, 256>>>(n);
    k_hist<<<(E + 255) / 256, 256>>>(dst, E);
    k_scan<<<1, 1024>>>(n);
    k_fill<<<(E + 255) / 256, 256>>>(src, dst, E);

    // layer 1
    k_agg<<<(n + 7) / 8, 256>>>(feat, (float*)px, n);
    k_gemm_relu<<<(n + 63) / 64, 256, SMEM_GEMM>>>((const float*)px, W1, b1, (float*)ph1, n);

    // layer 2
    k_agg<<<(n + 7) / 8, 256>>>((const float*)ph1, (float*)px, n);
    k_gemm_relu<<<(n + 63) / 64, 256, SMEM_GEMM>>>((const float*)px, W2, b2, (float*)ph2, n);

    // classifier + log_softmax
    k_final<<<(n + 63) / 64, 256, SMEM_FINAL>>>((const float*)ph1, (const float*)ph2,
                                                Wl, bl, out, n);
}

// round 6
// speedup vs baseline: 1.9615x; 1.9615x over previous
#include <cuda_runtime.h>
#include <math.h>
#include <stdint.h>

#define NN 100000
#define NE 1600000
#define DH 128
#define NC 64

// ---------------- scratch ----------------
__device__ int   g_deg[NN];
__device__ int   g_fill[NN];
__device__ int   g_rowptr[NN + 1];
__device__ float g_invdeg[NN];
__device__ int   g_adj[NE];
__device__ float g_x [(size_t)NN * DH];
__device__ float g_h1[(size_t)NN * DH];
__device__ float g_h2[(size_t)NN * DH];

__device__ __forceinline__ uint32_t f2tf(float f) {
    uint32_t u;
    asm("cvt.rna.tf32.f32 %0, %1;" : "=r"(u) : "f"(f));
    return u;
}

__device__ __forceinline__ void mma_tf32(float& d0, float& d1, float& d2, float& d3,
                                         uint32_t a0, uint32_t a1, uint32_t a2, uint32_t a3,
                                         uint32_t b0, uint32_t b1) {
    asm volatile(
        "mma.sync.aligned.m16n8k8.row.col.f32.tf32.tf32.f32 "
        "{%0,%1,%2,%3}, {%4,%5,%6,%7}, {%8,%9}, {%0,%1,%2,%3};\n"
        : "+f"(d0), "+f"(d1), "+f"(d2), "+f"(d3)
        : "r"(a0), "r"(a1), "r"(a2), "r"(a3), "r"(b0), "r"(b1));
}

// ---------------- CSR build ----------------
__global__ void k_zero(int n) {
    int i = blockIdx.x * blockDim.x + threadIdx.x;
    if (i < n) { g_deg[i] = 0; g_fill[i] = 0; }
}

__global__ void k_hist(const int* __restrict__ dst, int E) {
    int i = blockIdx.x * blockDim.x + threadIdx.x;
    if (i < E) atomicAdd(&g_deg[dst[i]], 1);
}

__global__ void k_scan(int n) {
    __shared__ int sums[1024];
    int tid = threadIdx.x;
    int per = (n + 1023) / 1024;
    int b = tid * per;
    int e = min(b + per, n);
    int s = 0;
    for (int i = b; i < e; i++) s += g_deg[i];
    sums[tid] = s;
    __syncthreads();
    for (int off = 1; off < 1024; off <<= 1) {
        int v = (tid >= off) ? sums[tid - off] : 0;
        __syncthreads();
        sums[tid] += v;
        __syncthreads();
    }
    int run = sums[tid] - s;
    for (int i = b; i < e; i++) {
        g_rowptr[i] = run;
        int d = g_deg[i];
        g_invdeg[i] = 1.0f / fmaxf((float)d, 1.0f);
        run += d;
    }
    if (tid == 1023) g_rowptr[n] = sums[1023];
}

__global__ void k_fill(const int* __restrict__ src, const int* __restrict__ dst, int E) {
    int i = blockIdx.x * blockDim.x + threadIdx.x;
    if (i < E) {
        int d = dst[i];
        int p = atomicAdd(&g_fill[d], 1);
        g_adj[g_rowptr[d] + p] = src[i];
    }
}

// ---------------- mean aggregation: 1 warp/node, unroll-4 for MLP ----------------
__global__ void k_agg(const float* __restrict__ feat, float* __restrict__ out, int n) {
    int node = blockIdx.x * (blockDim.x >> 5) + (threadIdx.x >> 5);
    if (node >= n) return;
    int lane = threadIdx.x & 31;
    int s = g_rowptr[node];
    int e = g_rowptr[node + 1];
    const float4* f4 = (const float4*)feat;
    float4 acc = make_float4(0.f, 0.f, 0.f, 0.f);
    int i = s;
    for (; i + 4 <= e; i += 4) {
        int j0 = g_adj[i], j1 = g_adj[i + 1], j2 = g_adj[i + 2], j3 = g_adj[i + 3];
        float4 v0 = f4[(size_t)j0 * 32 + lane];
        float4 v1 = f4[(size_t)j1 * 32 + lane];
        float4 v2 = f4[(size_t)j2 * 32 + lane];
        float4 v3 = f4[(size_t)j3 * 32 + lane];
        acc.x += (v0.x + v1.x) + (v2.x + v3.x);
        acc.y += (v0.y + v1.y) + (v2.y + v3.y);
        acc.z += (v0.z + v1.z) + (v2.z + v3.z);
        acc.w += (v0.w + v1.w) + (v2.w + v3.w);
    }
    for (; i < e; i++) {
        int j = g_adj[i];
        float4 v = f4[(size_t)j * 32 + lane];
        acc.x += v.x; acc.y += v.y; acc.z += v.z; acc.w += v.w;
    }
    float sc = g_invdeg[node];
    acc.x *= sc; acc.y *= sc; acc.z *= sc; acc.w *= sc;
    ((float4*)out)[(size_t)node * 32 + lane] = acc;
}

// ---------------- TF32 GEMM: out = relu(A[M,128] @ W[128,128]^T + b) ----------------
// Block = 64 rows. 8 warps: wm = w&3 (16 rows each), wn = w>>2 (64 cols each).
// Bs = W row-major [n][k] stride 132, As [r][k] stride 132  (frag LDS conflict-free:
// addr%32 = (4g+tg)%32, a permutation).
#define GSTRIDE 132
__global__ __launch_bounds__(256) void k_gemm_relu(
    const float* __restrict__ A, const float* __restrict__ W,
    const float* __restrict__ bias, float* __restrict__ out, int M) {
    extern __shared__ uint32_t smu[];
    uint32_t* Bs = smu;                  // 128 x 132
    uint32_t* As = smu + 128 * GSTRIDE;  // 64 x 132
    int tid = threadIdx.x;

    // fill Bs (float4 reads, tf32 convert)
    for (int idx = tid; idx < 128 * 32; idx += 256) {
        int nrow = idx >> 5, c4 = idx & 31;
        float4 v = ((const float4*)W)[idx];
        uint32_t* p = Bs + nrow * GSTRIDE + c4 * 4;
        p[0] = f2tf(v.x); p[1] = f2tf(v.y); p[2] = f2tf(v.z); p[3] = f2tf(v.w);
    }
    int row0 = blockIdx.x * 64;
    for (int idx = tid; idx < 64 * 32; idx += 256) {
        int r = idx >> 5, c4 = idx & 31;
        int row = row0 + r;
        float4 v = make_float4(0.f, 0.f, 0.f, 0.f);
        if (row < M) v = ((const float4*)A)[(size_t)row * 32 + c4];
        uint32_t* p = As + r * GSTRIDE + c4 * 4;
        p[0] = f2tf(v.x); p[1] = f2tf(v.y); p[2] = f2tf(v.z); p[3] = f2tf(v.w);
    }
    __syncthreads();

    int lane = tid & 31, w = tid >> 5;
    int wm = w & 3, wn = w >> 2;
    int g = lane >> 2, tg = lane & 3;
    int arow0 = (wm * 16 + g) * GSTRIDE;
    int arow1 = (wm * 16 + g + 8) * GSTRIDE;

    float d[8][4];
#pragma unroll
    for (int nt = 0; nt < 8; nt++)
#pragma unroll
        for (int c = 0; c < 4; c++) d[nt][c] = 0.f;

#pragma unroll 4
    for (int kt = 0; kt < 16; kt++) {
        int k0 = kt * 8;
        uint32_t a0 = As[arow0 + k0 + tg];
        uint32_t a1 = As[arow1 + k0 + tg];
        uint32_t a2 = As[arow0 + k0 + tg + 4];
        uint32_t a3 = As[arow1 + k0 + tg + 4];
#pragma unroll
        for (int nt = 0; nt < 8; nt++) {
            int nb = (wn * 64 + nt * 8 + g) * GSTRIDE + k0 + tg;
            uint32_t b0 = Bs[nb];
            uint32_t b1 = Bs[nb + 4];
            mma_tf32(d[nt][0], d[nt][1], d[nt][2], d[nt][3], a0, a1, a2, a3, b0, b1);
        }
    }

    int r0 = row0 + wm * 16 + g;
    int r1 = r0 + 8;
#pragma unroll
    for (int nt = 0; nt < 8; nt++) {
        int c = wn * 64 + nt * 8 + tg * 2;
        float bb0 = bias[c], bb1 = bias[c + 1];
        if (r0 < M) {
            float2 o;
            o.x = fmaxf(d[nt][0] + bb0, 0.f);
            o.y = fmaxf(d[nt][1] + bb1, 0.f);
            *(float2*)(out + (size_t)r0 * 128 + c) = o;
        }
        if (r1 < M) {
            float2 o;
            o.x = fmaxf(d[nt][2] + bb0, 0.f);
            o.y = fmaxf(d[nt][3] + bb1, 0.f);
            *(float2*)(out + (size_t)r1 * 128 + c) = o;
        }
    }
}

// ---------------- TF32 final: log_softmax([h1|h2] @ Wl^T + bl) ----------------
// Block = 128 rows, 8 warps, warp w owns rows [w*16, w*16+16) and ALL 64 cols
// (8 n-tiles), so each row's softmax reduces over one quad of lanes.
#define FSTRIDE 260
__global__ __launch_bounds__(256) void k_final(
    const float* __restrict__ h1, const float* __restrict__ h2,
    const float* __restrict__ W, const float* __restrict__ bias,
    float* __restrict__ out, int M) {
    extern __shared__ uint32_t smu[];
    uint32_t* Bs = smu;                 // 64 x 260
    uint32_t* As = smu + 64 * FSTRIDE;  // 128 x 260
    int tid = threadIdx.x;

    for (int idx = tid; idx < 64 * 64; idx += 256) {   // 64 rows x 64 float4
        int nrow = idx >> 6, c4 = idx & 63;
        float4 v = ((const float4*)W)[idx];
        uint32_t* p = Bs + nrow * FSTRIDE + c4 * 4;
        p[0] = f2tf(v.x); p[1] = f2tf(v.y); p[2] = f2tf(v.z); p[3] = f2tf(v.w);
    }
    int row0 = blockIdx.x * 128;
    for (int idx = tid; idx < 128 * 64; idx += 256) {  // 128 rows x 64 float4
        int r = idx >> 6, c4 = idx & 63;
        int row = row0 + r;
        float4 v = make_float4(0.f, 0.f, 0.f, 0.f);
        if (row < M) {
            if (c4 < 32) v = ((const float4*)h1)[(size_t)row * 32 + c4];
            else         v = ((const float4*)h2)[(size_t)row * 32 + (c4 - 32)];
        }
        uint32_t* p = As + r * FSTRIDE + c4 * 4;
        p[0] = f2tf(v.x); p[1] = f2tf(v.y); p[2] = f2tf(v.z); p[3] = f2tf(v.w);
    }
    __syncthreads();

    int lane = tid & 31, w = tid >> 5;
    int g = lane >> 2, tg = lane & 3;
    int arow0 = (w * 16 + g) * FSTRIDE;
    int arow1 = (w * 16 + g + 8) * FSTRIDE;

    float d[8][4];
#pragma unroll
    for (int nt = 0; nt < 8; nt++)
#pragma unroll
        for (int c = 0; c < 4; c++) d[nt][c] = 0.f;

#pragma unroll 4
    for (int kt = 0; kt < 32; kt++) {
        int k0 = kt * 8;
        uint32_t a0 = As[arow0 + k0 + tg];
        uint32_t a1 = As[arow1 + k0 + tg];
        uint32_t a2 = As[arow0 + k0 + tg + 4];
        uint32_t a3 = As[arow1 + k0 + tg + 4];
#pragma unroll
        for (int nt = 0; nt < 8; nt++) {
            int nb = (nt * 8 + g) * FSTRIDE + k0 + tg;
            uint32_t b0 = Bs[nb];
            uint32_t b1 = Bs[nb + 4];
            mma_tf32(d[nt][0], d[nt][1], d[nt][2], d[nt][3], a0, a1, a2, a3, b0, b1);
        }
    }

    // add bias -> logits: row r0 holds d[nt][0..1], row r1 holds d[nt][2..3]
    float x0[16], x1[16];
#pragma unroll
    for (int nt = 0; nt < 8; nt++) {
        int c = nt * 8 + tg * 2;
        float bb0 = bias[c], bb1 = bias[c + 1];
        x0[2 * nt]     = d[nt][0] + bb0;
        x0[2 * nt + 1] = d[nt][1] + bb1;
        x1[2 * nt]     = d[nt][2] + bb0;
        x1[2 * nt + 1] = d[nt][3] + bb1;
    }

    // log-softmax per row; full row lives in one quad (lanes tg=0..3 of group g)
    float m0 = -1e30f, m1 = -1e30f;
#pragma unroll
    for (int i = 0; i < 16; i++) { m0 = fmaxf(m0, x0[i]); m1 = fmaxf(m1, x1[i]); }
    m0 = fmaxf(m0, __shfl_xor_sync(0xffffffffu, m0, 1));
    m0 = fmaxf(m0, __shfl_xor_sync(0xffffffffu, m0, 2));
    m1 = fmaxf(m1, __shfl_xor_sync(0xffffffffu, m1, 1));
    m1 = fmaxf(m1, __shfl_xor_sync(0xffffffffu, m1, 2));
    float s0 = 0.f, s1 = 0.f;
#pragma unroll
    for (int i = 0; i < 16; i++) { s0 += expf(x0[i] - m0); s1 += expf(x1[i] - m1); }
    s0 += __shfl_xor_sync(0xffffffffu, s0, 1);
    s0 += __shfl_xor_sync(0xffffffffu, s0, 2);
    s1 += __shfl_xor_sync(0xffffffffu, s1, 1);
    s1 += __shfl_xor_sync(0xffffffffu, s1, 2);
    float ls0 = m0 + logf(s0);
    float ls1 = m1 + logf(s1);

    int r0 = row0 + w * 16 + g;
    int r1 = r0 + 8;
#pragma unroll
    for (int nt = 0; nt < 8; nt++) {
        int c = nt * 8 + tg * 2;
        if (r0 < M) {
            float2 o; o.x = x0[2 * nt] - ls0; o.y = x0[2 * nt + 1] - ls0;
            *(float2*)(out + (size_t)r0 * 64 + c) = o;
        }
        if (r1 < M) {
            float2 o; o.x = x1[2 * nt] - ls1; o.y = x1[2 * nt + 1] - ls1;
            *(float2*)(out + (size_t)r1 * 64 + c) = o;
        }
    }
}

// ---------------- launch ----------------
extern "C" void kernel_launch(void* const* d_in, const int* in_sizes, int n_in,
                              void* d_out, int out_size) {
    const float* feat = (const float*)d_in[0];
    const int*   src  = (const int*)d_in[1];
    const int*   dst  = (const int*)d_in[2];
    const float* W1   = (const float*)d_in[3];
    const float* b1   = (const float*)d_in[4];
    const float* W2   = (const float*)d_in[5];
    const float* b2   = (const float*)d_in[6];
    const float* Wl   = (const float*)d_in[7];
    const float* bl   = (const float*)d_in[8];
    float* out = (float*)d_out;

    int n = in_sizes[0] / DH;
    int E = in_sizes[1];

    void *px, *ph1, *ph2;
    cudaGetSymbolAddress(&px,  g_x);
    cudaGetSymbolAddress(&ph1, g_h1);
    cudaGetSymbolAddress(&ph2, g_h2);

    const int SMEM_GEMM  = (128 + 64) * GSTRIDE * 4;   // 101376 B
    const int SMEM_FINAL = (64 + 128) * FSTRIDE * 4;   // 199680 B
    cudaFuncSetAttribute(k_gemm_relu, cudaFuncAttributeMaxDynamicSharedMemorySize, SMEM_GEMM);
    cudaFuncSetAttribute(k_final,     cudaFuncAttributeMaxDynamicSharedMemorySize, SMEM_FINAL);

    // CSR build
    k_zero<<<(n + 255) / 256, 256>>>(n);
    k_hist<<<(E + 255) / 256, 256>>>(dst, E);
    k_scan<<<1, 1024>>>(n);
    k_fill<<<(E + 255) / 256, 256>>>(src, dst, E);

    // layer 1
    k_agg<<<(n + 7) / 8, 256>>>(feat, (float*)px, n);
    k_gemm_relu<<<(n + 63) / 64, 256, SMEM_GEMM>>>((const float*)px, W1, b1, (float*)ph1, n);

    // layer 2
    k_agg<<<(n + 7) / 8, 256>>>((const float*)ph1, (float*)px, n);
    k_gemm_relu<<<(n + 63) / 64, 256, SMEM_GEMM>>>((const float*)px, W2, b2, (float*)ph2, n);

    // classifier + log_softmax
    k_final<<<(n + 127) / 128, 256, SMEM_FINAL>>>((const float*)ph1, (const float*)ph2,
                                                  Wl, bl, out, n);
}

// round 8
// speedup vs baseline: 2.8000x; 1.4274x over previous
#include <cuda_runtime.h>
#include <cuda_bf16.h>
#include <math.h>
#include <stdint.h>

#define NN 100000
#define NE 1600000
#define DH 128
#define NC 64

// ---------------- scratch ----------------
__device__ int   g_deg[NN];
__device__ int   g_fill[NN];
__device__ int   g_rowptr[NN + 1];
__device__ float g_invdeg[NN];
__device__ int   g_adj[NE];
__device__ __nv_bfloat16 g_fb [(size_t)NN * DH];  // feat in bf16
__device__ __nv_bfloat16 g_xb [(size_t)NN * DH];  // aggregated (bf16)
__device__ __nv_bfloat16 g_h1b[(size_t)NN * DH];
__device__ __nv_bfloat16 g_h2b[(size_t)NN * DH];

__device__ __forceinline__ uint32_t pack_bf2(float x, float y) {
    __nv_bfloat162 h = __floats2bfloat162_rn(x, y);
    return *reinterpret_cast<uint32_t*>(&h);
}
__device__ __forceinline__ float2 unpack_bf2(uint32_t u) {
    __nv_bfloat162 h = *reinterpret_cast<__nv_bfloat162*>(&u);
    return __bfloat1622float2(h);
}

__device__ __forceinline__ void mma_bf16(float& d0, float& d1, float& d2, float& d3,
                                         uint32_t a0, uint32_t a1, uint32_t a2, uint32_t a3,
                                         uint32_t b0, uint32_t b1) {
    asm volatile(
        "mma.sync.aligned.m16n8k16.row.col.f32.bf16.bf16.f32 "
        "{%0,%1,%2,%3}, {%4,%5,%6,%7}, {%8,%9}, {%0,%1,%2,%3};\n"
        : "+f"(d0), "+f"(d1), "+f"(d2), "+f"(d3)
        : "r"(a0), "r"(a1), "r"(a2), "r"(a3), "r"(b0), "r"(b1));
}

// ---------------- CSR build ----------------
__global__ void k_zero(int n) {
    int i = blockIdx.x * blockDim.x + threadIdx.x;
    if (i < n) { g_deg[i] = 0; g_fill[i] = 0; }
}

__global__ void k_hist(const int* __restrict__ dst, int E) {
    int i = blockIdx.x * blockDim.x + threadIdx.x;
    if (i < E) atomicAdd(&g_deg[dst[i]], 1);
}

__global__ void k_scan(int n) {
    __shared__ int sums[1024];
    int tid = threadIdx.x;
    int per = (n + 1023) / 1024;
    int b = tid * per;
    int e = min(b + per, n);
    int s = 0;
    for (int i = b; i < e; i++) s += g_deg[i];
    sums[tid] = s;
    __syncthreads();
    for (int off = 1; off < 1024; off <<= 1) {
        int v = (tid >= off) ? sums[tid - off] : 0;
        __syncthreads();
        sums[tid] += v;
        __syncthreads();
    }
    int run = sums[tid] - s;
    for (int i = b; i < e; i++) {
        g_rowptr[i] = run;
        int d = g_deg[i];
        g_invdeg[i] = 1.0f / fmaxf((float)d, 1.0f);
        run += d;
    }
    if (tid == 1023) g_rowptr[n] = sums[1023];
}

__global__ void k_fill(const int* __restrict__ src, const int* __restrict__ dst, int E) {
    int i = blockIdx.x * blockDim.x + threadIdx.x;
    if (i < E) {
        int d = dst[i];
        int p = atomicAdd(&g_fill[d], 1);
        g_adj[g_rowptr[d] + p] = src[i];
    }
}

// ---------------- feat fp32 -> bf16 ----------------
__global__ void k_cvt(const float4* __restrict__ in, uint2* __restrict__ out, int n4) {
    int i = blockIdx.x * blockDim.x + threadIdx.x;
    int stride = gridDim.x * blockDim.x;
    for (; i < n4; i += stride) {
        float4 v = in[i];
        uint2 o;
        o.x = pack_bf2(v.x, v.y);
        o.y = pack_bf2(v.z, v.w);
        out[i] = o;
    }
}

// ---------------- mean aggregation over bf16 rows: 1 warp/node ----------------
// Row = 128 bf16 = 256B; lane handles 4 features via one uint2 load.
__global__ void k_agg(const __nv_bfloat16* __restrict__ feat,
                      __nv_bfloat16* __restrict__ out, int n) {
    int node = blockIdx.x * (blockDim.x >> 5) + (threadIdx.x >> 5);
    if (node >= n) return;
    int lane = threadIdx.x & 31;
    int s = g_rowptr[node];
    int e = g_rowptr[node + 1];
    const uint2* f2 = (const uint2*)feat;
    float4 acc = make_float4(0.f, 0.f, 0.f, 0.f);
    int i = s;
    for (; i + 4 <= e; i += 4) {
        int j0 = g_adj[i], j1 = g_adj[i + 1], j2 = g_adj[i + 2], j3 = g_adj[i + 3];
        uint2 v0 = f2[(size_t)j0 * 32 + lane];
        uint2 v1 = f2[(size_t)j1 * 32 + lane];
        uint2 v2 = f2[(size_t)j2 * 32 + lane];
        uint2 v3 = f2[(size_t)j3 * 32 + lane];
        float2 a0 = unpack_bf2(v0.x), b0 = unpack_bf2(v0.y);
        float2 a1 = unpack_bf2(v1.x), b1 = unpack_bf2(v1.y);
        float2 a2 = unpack_bf2(v2.x), b2 = unpack_bf2(v2.y);
        float2 a3 = unpack_bf2(v3.x), b3 = unpack_bf2(v3.y);
        acc.x += (a0.x + a1.x) + (a2.x + a3.x);
        acc.y += (a0.y + a1.y) + (a2.y + a3.y);
        acc.z += (b0.x + b1.x) + (b2.x + b3.x);
        acc.w += (b0.y + b1.y) + (b2.y + b3.y);
    }
    for (; i < e; i++) {
        int j = g_adj[i];
        uint2 v = f2[(size_t)j * 32 + lane];
        float2 a = unpack_bf2(v.x), b = unpack_bf2(v.y);
        acc.x += a.x; acc.y += a.y; acc.z += b.x; acc.w += b.y;
    }
    float sc = g_invdeg[node];
    uint2 o;
    o.x = pack_bf2(acc.x * sc, acc.y * sc);
    o.y = pack_bf2(acc.z * sc, acc.w * sc);
    ((uint2*)out)[(size_t)node * 32 + lane] = o;
}

// ---------------- bf16 GEMM: out = relu(A[M,128] @ W[128,128]^T + b) ----------------
// Block = 64 rows, 8 warps: wm = w&3 (16 rows), wn = w>>2 (64 cols).
// Smem bf16 stored as u32 pairs, row stride 68 u32 (== 4 mod 32 -> frag LDS
// address (4g+tg)%32 = lane, conflict-free).
#define GSTR 68
__global__ __launch_bounds__(256) void k_gemm_relu(
    const __nv_bfloat16* __restrict__ A, const float* __restrict__ W,
    const float* __restrict__ bias, __nv_bfloat16* __restrict__ out, int M) {
    extern __shared__ uint32_t smu[];
    uint32_t* Bs = smu;               // 128 x 68 u32 (= 128 x 136 bf16)
    uint32_t* As = smu + 128 * GSTR;  // 64 x 68
    int tid = threadIdx.x;

    // W fp32 -> bf16 smem, [n][k]
    for (int idx = tid; idx < 128 * 32; idx += 256) {
        int nrow = idx >> 5, c4 = idx & 31;
        float4 v = ((const float4*)W)[idx];
        uint2 o; o.x = pack_bf2(v.x, v.y); o.y = pack_bf2(v.z, v.w);
        *(uint2*)(Bs + nrow * GSTR + c4 * 2) = o;
    }
    int row0 = blockIdx.x * 64;
    for (int idx = tid; idx < 64 * 16; idx += 256) {   // 16 uint4 per 256B row
        int r = idx >> 4, c = idx & 15;
        int row = row0 + r;
        uint4 v = make_uint4(0u, 0u, 0u, 0u);
        if (row < M) v = ((const uint4*)A)[(size_t)row * 16 + c];
        *(uint4*)(As + r * GSTR + c * 4) = v;
    }
    __syncthreads();

    int lane = tid & 31, w = tid >> 5;
    int wm = w & 3, wn = w >> 2;
    int g = lane >> 2, tg = lane & 3;
    int arow0 = (wm * 16 + g) * GSTR;
    int arow1 = (wm * 16 + g + 8) * GSTR;

    float d[8][4];
#pragma unroll
    for (int nt = 0; nt < 8; nt++)
#pragma unroll
        for (int c = 0; c < 4; c++) d[nt][c] = 0.f;

#pragma unroll
    for (int kt = 0; kt < 8; kt++) {
        int k0 = kt * 8;
        uint32_t a0 = As[arow0 + k0 + tg];
        uint32_t a1 = As[arow1 + k0 + tg];
        uint32_t a2 = As[arow0 + k0 + tg + 4];
        uint32_t a3 = As[arow1 + k0 + tg + 4];
#pragma unroll
        for (int nt = 0; nt < 8; nt++) {
            int nb = (wn * 64 + nt * 8 + g) * GSTR + k0 + tg;
            uint32_t b0 = Bs[nb];
            uint32_t b1 = Bs[nb + 4];
            mma_bf16(d[nt][0], d[nt][1], d[nt][2], d[nt][3], a0, a1, a2, a3, b0, b1);
        }
    }

    int r0 = row0 + wm * 16 + g;
    int r1 = r0 + 8;
#pragma unroll
    for (int nt = 0; nt < 8; nt++) {
        int c = wn * 64 + nt * 8 + tg * 2;
        float bb0 = bias[c], bb1 = bias[c + 1];
        if (r0 < M)
            *(uint32_t*)(out + (size_t)r0 * 128 + c) =
                pack_bf2(fmaxf(d[nt][0] + bb0, 0.f), fmaxf(d[nt][1] + bb1, 0.f));
        if (r1 < M)
            *(uint32_t*)(out + (size_t)r1 * 128 + c) =
                pack_bf2(fmaxf(d[nt][2] + bb0, 0.f), fmaxf(d[nt][3] + bb1, 0.f));
    }
}

// ---------------- bf16 final: log_softmax([h1|h2] @ Wl^T + bl) ----------------
// Block = 128 rows, 8 warps; warp w owns rows [w*16, w*16+16) x all 64 cols.
#define FSTR 132
__global__ __launch_bounds__(256) void k_final(
    const __nv_bfloat16* __restrict__ h1, const __nv_bfloat16* __restrict__ h2,
    const float* __restrict__ W, const float* __restrict__ bias,
    float* __restrict__ out, int M) {
    extern __shared__ uint32_t smu[];
    uint32_t* Bs = smu;              // 64 x 132 u32
    uint32_t* As = smu + 64 * FSTR;  // 128 x 132
    int tid = threadIdx.x;

    for (int idx = tid; idx < 64 * 64; idx += 256) {   // Wl: 64 rows x 64 float4
        int nrow = idx >> 6, c4 = idx & 63;
        float4 v = ((const float4*)W)[idx];
        uint2 o; o.x = pack_bf2(v.x, v.y); o.y = pack_bf2(v.z, v.w);
        *(uint2*)(Bs + nrow * FSTR + c4 * 2) = o;
    }
    int row0 = blockIdx.x * 128;
    for (int idx = tid; idx < 128 * 32; idx += 256) {  // 32 uint4 per 512B row
        int r = idx >> 5, c = idx & 31;
        int row = row0 + r;
        uint4 v = make_uint4(0u, 0u, 0u, 0u);
        if (row < M) {
            if (c < 16) v = ((const uint4*)h1)[(size_t)row * 16 + c];
            else        v = ((const uint4*)h2)[(size_t)row * 16 + (c - 16)];
        }
        *(uint4*)(As + r * FSTR + c * 4) = v;
    }
    __syncthreads();

    int lane = tid & 31, w = tid >> 5;
    int g = lane >> 2, tg = lane & 3;
    int arow0 = (w * 16 + g) * FSTR;
    int arow1 = (w * 16 + g + 8) * FSTR;

    float d[8][4];
#pragma unroll
    for (int nt = 0; nt < 8; nt++)
#pragma unroll
        for (int c = 0; c < 4; c++) d[nt][c] = 0.f;

#pragma unroll
    for (int kt = 0; kt < 16; kt++) {
        int k0 = kt * 8;
        uint32_t a0 = As[arow0 + k0 + tg];
        uint32_t a1 = As[arow1 + k0 + tg];
        uint32_t a2 = As[arow0 + k0 + tg + 4];
        uint32_t a3 = As[arow1 + k0 + tg + 4];
#pragma unroll
        for (int nt = 0; nt < 8; nt++) {
            int nb = (nt * 8 + g) * FSTR + k0 + tg;
            uint32_t b0 = Bs[nb];
            uint32_t b1 = Bs[nb + 4];
            mma_bf16(d[nt][0], d[nt][1], d[nt][2], d[nt][3], a0, a1, a2, a3, b0, b1);
        }
    }

    float x0[16], x1[16];
#pragma unroll
    for (int nt = 0; nt < 8; nt++) {
        int c = nt * 8 + tg * 2;
        float bb0 = bias[c], bb1 = bias[c + 1];
        x0[2 * nt]     = d[nt][0] + bb0;
        x0[2 * nt + 1] = d[nt][1] + bb1;
        x1[2 * nt]     = d[nt][2] + bb0;
        x1[2 * nt + 1] = d[nt][3] + bb1;
    }

    float m0 = -1e30f, m1 = -1e30f;
#pragma unroll
    for (int i = 0; i < 16; i++) { m0 = fmaxf(m0, x0[i]); m1 = fmaxf(m1, x1[i]); }
    m0 = fmaxf(m0, __shfl_xor_sync(0xffffffffu, m0, 1));
    m0 = fmaxf(m0, __shfl_xor_sync(0xffffffffu, m0, 2));
    m1 = fmaxf(m1, __shfl_xor_sync(0xffffffffu, m1, 1));
    m1 = fmaxf(m1, __shfl_xor_sync(0xffffffffu, m1, 2));
    float s0 = 0.f, s1 = 0.f;
#pragma unroll
    for (int i = 0; i < 16; i++) { s0 += expf(x0[i] - m0); s1 += expf(x1[i] - m1); }
    s0 += __shfl_xor_sync(0xffffffffu, s0, 1);
    s0 += __shfl_xor_sync(0xffffffffu, s0, 2);
    s1 += __shfl_xor_sync(0xffffffffu, s1, 1);
    s1 += __shfl_xor_sync(0xffffffffu, s1, 2);
    float ls0 = m0 + logf(s0);
    float ls1 = m1 + logf(s1);

    int r0 = row0 + w * 16 + g;
    int r1 = r0 + 8;
#pragma unroll
    for (int nt = 0; nt < 8; nt++) {
        int c = nt * 8 + tg * 2;
        if (r0 < M) {
            float2 o; o.x = x0[2 * nt] - ls0; o.y = x0[2 * nt + 1] - ls0;
            *(float2*)(out + (size_t)r0 * 64 + c) = o;
        }
        if (r1 < M) {
            float2 o; o.x = x1[2 * nt] - ls1; o.y = x1[2 * nt + 1] - ls1;
            *(float2*)(out + (size_t)r1 * 64 + c) = o;
        }
    }
}

// ---------------- launch ----------------
extern "C" void kernel_launch(void* const* d_in, const int* in_sizes, int n_in,
                              void* d_out, int out_size) {
    const float* feat = (const float*)d_in[0];
    const int*   src  = (const int*)d_in[1];
    const int*   dst  = (const int*)d_in[2];
    const float* W1   = (const float*)d_in[3];
    const float* b1   = (const float*)d_in[4];
    const float* W2   = (const float*)d_in[5];
    const float* b2   = (const float*)d_in[6];
    const float* Wl   = (const float*)d_in[7];
    const float* bl   = (const float*)d_in[8];
    float* out = (float*)d_out;

    int n = in_sizes[0] / DH;
    int E = in_sizes[1];

    void *pfb, *pxb, *ph1, *ph2;
    cudaGetSymbolAddress(&pfb, g_fb);
    cudaGetSymbolAddress(&pxb, g_xb);
    cudaGetSymbolAddress(&ph1, g_h1b);
    cudaGetSymbolAddress(&ph2, g_h2b);

    const int SMEM_GEMM  = (128 + 64) * GSTR * 4;   //  52224 B
    const int SMEM_FINAL = (64 + 128) * FSTR * 4;   // 101376 B
    cudaFuncSetAttribute(k_gemm_relu, cudaFuncAttributeMaxDynamicSharedMemorySize, SMEM_GEMM);
    cudaFuncSetAttribute(k_final,     cudaFuncAttributeMaxDynamicSharedMemorySize, SMEM_FINAL);

    // CSR build
    k_zero<<<(n + 255) / 256, 256>>>(n);
    k_hist<<<(E + 255) / 256, 256>>>(dst, E);
    k_scan<<<1, 1024>>>(n);
    k_fill<<<(E + 255) / 256, 256>>>(src, dst, E);

    // feat -> bf16
    k_cvt<<<512, 256>>>((const float4*)feat, (uint2*)pfb, n * DH / 4);

    // layer 1
    k_agg<<<(n + 7) / 8, 256>>>((const __nv_bfloat16*)pfb, (__nv_bfloat16*)pxb, n);
    k_gemm_relu<<<(n + 63) / 64, 256, SMEM_GEMM>>>((const __nv_bfloat16*)pxb, W1, b1,
                                                   (__nv_bfloat16*)ph1, n);

    // layer 2
    k_agg<<<(n + 7) / 8, 256>>>((const __nv_bfloat16*)ph1, (__nv_bfloat16*)pxb, n);
    k_gemm_relu<<<(n + 63) / 64, 256, SMEM_GEMM>>>((const __nv_bfloat16*)pxb, W2, b2,
                                                   (__nv_bfloat16*)ph2, n);

    // classifier + log_softmax
    k_final<<<(n + 127) / 128, 256, SMEM_FINAL>>>((const __nv_bfloat16*)ph1,
                                                  (const __nv_bfloat16*)ph2,
                                                  Wl, bl, out, n);
}

// round 10
// speedup vs baseline: 3.0155x; 1.0770x over previous
#include <cuda_runtime.h>
#include <cuda_bf16.h>
#include <math.h>
#include <stdint.h>

#define NN 100000
#define NE 1600000
#define DH 128
#define NC 64

// ---------------- scratch ----------------
__device__ int   g_deg[NN];
__device__ int   g_fill[NN];
__device__ int   g_rowptr[NN + 1];
__device__ float g_invdeg[NN];
__device__ int   g_adj[NE];
__device__ __nv_bfloat16 g_fb [(size_t)NN * DH];  // feat in bf16
__device__ __nv_bfloat16 g_xb [(size_t)NN * DH];  // aggregated (bf16)
__device__ __nv_bfloat16 g_h1b[(size_t)NN * DH];
__device__ __nv_bfloat16 g_h2b[(size_t)NN * DH];
__device__ __nv_bfloat16 g_w1b[DH * DH];
__device__ __nv_bfloat16 g_w2b[DH * DH];
__device__ __nv_bfloat16 g_wlb[NC * 2 * DH];

__device__ __forceinline__ uint32_t pack_bf2(float x, float y) {
    __nv_bfloat162 h = __floats2bfloat162_rn(x, y);
    return *reinterpret_cast<uint32_t*>(&h);
}
__device__ __forceinline__ float2 unpack_bf2(uint32_t u) {
    __nv_bfloat162 h = *reinterpret_cast<__nv_bfloat162*>(&u);
    return __bfloat1622float2(h);
}
__device__ __forceinline__ void acc8(float* a, uint4 v) {
    float2 p;
    p = unpack_bf2(v.x); a[0] += p.x; a[1] += p.y;
    p = unpack_bf2(v.y); a[2] += p.x; a[3] += p.y;
    p = unpack_bf2(v.z); a[4] += p.x; a[5] += p.y;
    p = unpack_bf2(v.w); a[6] += p.x; a[7] += p.y;
}

__device__ __forceinline__ void mma_bf16(float& d0, float& d1, float& d2, float& d3,
                                         uint32_t a0, uint32_t a1, uint32_t a2, uint32_t a3,
                                         uint32_t b0, uint32_t b1) {
    asm volatile(
        "mma.sync.aligned.m16n8k16.row.col.f32.bf16.bf16.f32 "
        "{%0,%1,%2,%3}, {%4,%5,%6,%7}, {%8,%9}, {%0,%1,%2,%3};\n"
        : "+f"(d0), "+f"(d1), "+f"(d2), "+f"(d3)
        : "r"(a0), "r"(a1), "r"(a2), "r"(a3), "r"(b0), "r"(b1));
}

// ---------------- CSR build ----------------
__global__ void k_zero(int n) {
    int i = blockIdx.x * blockDim.x + threadIdx.x;
    if (i < n) { g_deg[i] = 0; g_fill[i] = 0; }
}

__global__ void k_hist(const int* __restrict__ dst, int E) {
    int i = blockIdx.x * blockDim.x + threadIdx.x;
    if (i < E) atomicAdd(&g_deg[dst[i]], 1);
}

__global__ void k_scan(int n) {
    __shared__ int sums[1024];
    int tid = threadIdx.x;
    int per = (n + 1023) / 1024;
    int b = tid * per;
    int e = min(b + per, n);
    int s = 0;
    for (int i = b; i < e; i++) s += g_deg[i];
    sums[tid] = s;
    __syncthreads();
    for (int off = 1; off < 1024; off <<= 1) {
        int v = (tid >= off) ? sums[tid - off] : 0;
        __syncthreads();
        sums[tid] += v;
        __syncthreads();
    }
    int run = sums[tid] - s;
    for (int i = b; i < e; i++) {
        g_rowptr[i] = run;
        int d = g_deg[i];
        g_invdeg[i] = 1.0f / fmaxf((float)d, 1.0f);
        run += d;
    }
    if (tid == 1023) g_rowptr[n] = sums[1023];
}

__global__ void k_fill(const int* __restrict__ src, const int* __restrict__ dst, int E) {
    int i = blockIdx.x * blockDim.x + threadIdx.x;
    if (i < E) {
        int d = dst[i];
        int p = atomicAdd(&g_fill[d], 1);
        g_adj[g_rowptr[d] + p] = src[i];
    }
}

// ---------------- fp32 -> bf16 convert ----------------
__global__ void k_cvt(const float4* __restrict__ in, uint2* __restrict__ out, int n4) {
    int i = blockIdx.x * blockDim.x + threadIdx.x;
    int stride = gridDim.x * blockDim.x;
    for (; i < n4; i += stride) {
        float4 v = in[i];
        uint2 o;
        o.x = pack_bf2(v.x, v.y);
        o.y = pack_bf2(v.z, v.w);
        out[i] = o;
    }
}

// ---------------- mean aggregation: 2 nodes/warp, 16 lanes/node, uint4 loads ------
// Row = 128 bf16 = 256B = 16 uint4; lane hl covers 8 features. Unroll-4 ->
// 4 outstanding 16B loads per lane (64B in flight).
__global__ void k_agg(const __nv_bfloat16* __restrict__ feat,
                      __nv_bfloat16* __restrict__ out, int n) {
    int warp = blockIdx.x * (blockDim.x >> 5) + (threadIdx.x >> 5);
    int lane = threadIdx.x & 31;
    int node = warp * 2 + (lane >> 4);
    if (node >= n) return;
    int hl = lane & 15;
    int s = g_rowptr[node];
    int e = g_rowptr[node + 1];
    const uint4* f4 = (const uint4*)feat;
    float acc[8];
#pragma unroll
    for (int k = 0; k < 8; k++) acc[k] = 0.f;
    int i = s;
    for (; i + 4 <= e; i += 4) {
        int j0 = g_adj[i], j1 = g_adj[i + 1], j2 = g_adj[i + 2], j3 = g_adj[i + 3];
        uint4 v0 = f4[(size_t)j0 * 16 + hl];
        uint4 v1 = f4[(size_t)j1 * 16 + hl];
        uint4 v2 = f4[(size_t)j2 * 16 + hl];
        uint4 v3 = f4[(size_t)j3 * 16 + hl];
        acc8(acc, v0); acc8(acc, v1); acc8(acc, v2); acc8(acc, v3);
    }
    for (; i < e; i++) {
        uint4 v = f4[(size_t)g_adj[i] * 16 + hl];
        acc8(acc, v);
    }
    float sc = g_invdeg[node];
    uint4 o;
    o.x = pack_bf2(acc[0] * sc, acc[1] * sc);
    o.y = pack_bf2(acc[2] * sc, acc[3] * sc);
    o.z = pack_bf2(acc[4] * sc, acc[5] * sc);
    o.w = pack_bf2(acc[6] * sc, acc[7] * sc);
    ((uint4*)out)[(size_t)node * 16 + hl] = o;
}

// ---------------- bf16 GEMM: out = relu(A[M,128] @ W[128,128]^T + b) ----------------
// Block = 64 rows, 8 warps: wm = w&3 (16 rows), wn = w>>2 (64 cols).
// Smem u32 row stride 68 (== 4 mod 32 -> frag LDS conflict-free).
#define GSTR 68
__global__ __launch_bounds__(256) void k_gemm_relu(
    const __nv_bfloat16* __restrict__ A, const __nv_bfloat16* __restrict__ Wb,
    const float* __restrict__ bias, __nv_bfloat16* __restrict__ out, int M) {
    extern __shared__ uint32_t smu[];
    uint32_t* Bs = smu;               // 128 x 68 u32
    uint32_t* As = smu + 128 * GSTR;  // 64 x 68
    int tid = threadIdx.x;

    // W already bf16: pure uint4 copy, [n][k]
    for (int idx = tid; idx < 128 * 16; idx += 256) {
        int nrow = idx >> 4, c = idx & 15;
        uint4 v = ((const uint4*)Wb)[idx];
        *(uint4*)(Bs + nrow * GSTR + c * 4) = v;
    }
    int row0 = blockIdx.x * 64;
    for (int idx = tid; idx < 64 * 16; idx += 256) {
        int r = idx >> 4, c = idx & 15;
        int row = row0 + r;
        uint4 v = make_uint4(0u, 0u, 0u, 0u);
        if (row < M) v = ((const uint4*)A)[(size_t)row * 16 + c];
        *(uint4*)(As + r * GSTR + c * 4) = v;
    }
    __syncthreads();

    int lane = tid & 31, w = tid >> 5;
    int wm = w & 3, wn = w >> 2;
    int g = lane >> 2, tg = lane & 3;
    int arow0 = (wm * 16 + g) * GSTR;
    int arow1 = (wm * 16 + g + 8) * GSTR;

    float d[8][4];
#pragma unroll
    for (int nt = 0; nt < 8; nt++)
#pragma unroll
        for (int c = 0; c < 4; c++) d[nt][c] = 0.f;

#pragma unroll
    for (int kt = 0; kt < 8; kt++) {
        int k0 = kt * 8;
        uint32_t a0 = As[arow0 + k0 + tg];
        uint32_t a1 = As[arow1 + k0 + tg];
        uint32_t a2 = As[arow0 + k0 + tg + 4];
        uint32_t a3 = As[arow1 + k0 + tg + 4];
#pragma unroll
        for (int nt = 0; nt < 8; nt++) {
            int nb = (wn * 64 + nt * 8 + g) * GSTR + k0 + tg;
            uint32_t b0 = Bs[nb];
            uint32_t b1 = Bs[nb + 4];
            mma_bf16(d[nt][0], d[nt][1], d[nt][2], d[nt][3], a0, a1, a2, a3, b0, b1);
        }
    }

    int r0 = row0 + wm * 16 + g;
    int r1 = r0 + 8;
#pragma unroll
    for (int nt = 0; nt < 8; nt++) {
        int c = wn * 64 + nt * 8 + tg * 2;
        float bb0 = bias[c], bb1 = bias[c + 1];
        if (r0 < M)
            *(uint32_t*)(out + (size_t)r0 * 128 + c) =
                pack_bf2(fmaxf(d[nt][0] + bb0, 0.f), fmaxf(d[nt][1] + bb1, 0.f));
        if (r1 < M)
            *(uint32_t*)(out + (size_t)r1 * 128 + c) =
                pack_bf2(fmaxf(d[nt][2] + bb0, 0.f), fmaxf(d[nt][3] + bb1, 0.f));
    }
}

// ---------------- bf16 final: log_softmax([h1|h2] @ Wl^T + bl) ----------------
// Block = 128 rows, 8 warps; warp w owns rows [w*16, w*16+16) x all 64 cols.
#define FSTR 132
__global__ __launch_bounds__(256) void k_final(
    const __nv_bfloat16* __restrict__ h1, const __nv_bfloat16* __restrict__ h2,
    const __nv_bfloat16* __restrict__ Wb, const float* __restrict__ bias,
    float* __restrict__ out, int M) {
    extern __shared__ uint32_t smu[];
    uint32_t* Bs = smu;              // 64 x 132 u32
    uint32_t* As = smu + 64 * FSTR;  // 128 x 132
    int tid = threadIdx.x;

    for (int idx = tid; idx < 64 * 32; idx += 256) {   // Wl bf16: 64 rows x 32 uint4
        int nrow = idx >> 5, c = idx & 31;
        uint4 v = ((const uint4*)Wb)[idx];
        *(uint4*)(Bs + nrow * FSTR + c * 4) = v;
    }
    int row0 = blockIdx.x * 128;
    for (int idx = tid; idx < 128 * 32; idx += 256) {  // 32 uint4 per 512B row
        int r = idx >> 5, c = idx & 31;
        int row = row0 + r;
        uint4 v = make_uint4(0u, 0u, 0u, 0u);
        if (row < M) {
            if (c < 16) v = ((const uint4*)h1)[(size_t)row * 16 + c];
            else        v = ((const uint4*)h2)[(size_t)row * 16 + (c - 16)];
        }
        *(uint4*)(As + r * FSTR + c * 4) = v;
    }
    __syncthreads();

    int lane = tid & 31, w = tid >> 5;
    int g = lane >> 2, tg = lane & 3;
    int arow0 = (w * 16 + g) * FSTR;
    int arow1 = (w * 16 + g + 8) * FSTR;

    float d[8][4];
#pragma unroll
    for (int nt = 0; nt < 8; nt++)
#pragma unroll
        for (int c = 0; c < 4; c++) d[nt][c] = 0.f;

#pragma unroll
    for (int kt = 0; kt < 16; kt++) {
        int k0 = kt * 8;
        uint32_t a0 = As[arow0 + k0 + tg];
        uint32_t a1 = As[arow1 + k0 + tg];
        uint32_t a2 = As[arow0 + k0 + tg + 4];
        uint32_t a3 = As[arow1 + k0 + tg + 4];
#pragma unroll
        for (int nt = 0; nt < 8; nt++) {
            int nb = (nt * 8 + g) * FSTR + k0 + tg;
            uint32_t b0 = Bs[nb];
            uint32_t b1 = Bs[nb + 4];
            mma_bf16(d[nt][0], d[nt][1], d[nt][2], d[nt][3], a0, a1, a2, a3, b0, b1);
        }
    }

    float x0[16], x1[16];
#pragma unroll
    for (int nt = 0; nt < 8; nt++) {
        int c = nt * 8 + tg * 2;
        float bb0 = bias[c], bb1 = bias[c + 1];
        x0[2 * nt]     = d[nt][0] + bb0;
        x0[2 * nt + 1] = d[nt][1] + bb1;
        x1[2 * nt]     = d[nt][2] + bb0;
        x1[2 * nt + 1] = d[nt][3] + bb1;
    }

    float m0 = -1e30f, m1 = -1e30f;
#pragma unroll
    for (int i = 0; i < 16; i++) { m0 = fmaxf(m0, x0[i]); m1 = fmaxf(m1, x1[i]); }
    m0 = fmaxf(m0, __shfl_xor_sync(0xffffffffu, m0, 1));
    m0 = fmaxf(m0, __shfl_xor_sync(0xffffffffu, m0, 2));
    m1 = fmaxf(m1, __shfl_xor_sync(0xffffffffu, m1, 1));
    m1 = fmaxf(m1, __shfl_xor_sync(0xffffffffu, m1, 2));
    float s0 = 0.f, s1 = 0.f;
#pragma unroll
    for (int i = 0; i < 16; i++) { s0 += expf(x0[i] - m0); s1 += expf(x1[i] - m1); }
    s0 += __shfl_xor_sync(0xffffffffu, s0, 1);
    s0 += __shfl_xor_sync(0xffffffffu, s0, 2);
    s1 += __shfl_xor_sync(0xffffffffu, s1, 1);
    s1 += __shfl_xor_sync(0xffffffffu, s1, 2);
    float ls0 = m0 + logf(s0);
    float ls1 = m1 + logf(s1);

    int r0 = row0 + w * 16 + g;
    int r1 = r0 + 8;
#pragma unroll
    for (int nt = 0; nt < 8; nt++) {
        int c = nt * 8 + tg * 2;
        if (r0 < M) {
            float2 o; o.x = x0[2 * nt] - ls0; o.y = x0[2 * nt + 1] - ls0;
            *(float2*)(out + (size_t)r0 * 64 + c) = o;
        }
        if (r1 < M) {
            float2 o; o.x = x1[2 * nt] - ls1; o.y = x1[2 * nt + 1] - ls1;
            *(float2*)(out + (size_t)r1 * 64 + c) = o;
        }
    }
}

// ---------------- launch ----------------
extern "C" void kernel_launch(void* const* d_in, const int* in_sizes, int n_in,
                              void* d_out, int out_size) {
    const float* feat = (const float*)d_in[0];
    const int*   src  = (const int*)d_in[1];
    const int*   dst  = (const int*)d_in[2];
    const float* W1   = (const float*)d_in[3];
    const float* b1   = (const float*)d_in[4];
    const float* W2   = (const float*)d_in[5];
    const float* b2   = (const float*)d_in[6];
    const float* Wl   = (const float*)d_in[7];
    const float* bl   = (const float*)d_in[8];
    float* out = (float*)d_out;

    int n = in_sizes[0] / DH;
    int E = in_sizes[1];

    void *pfb, *pxb, *ph1, *ph2, *pw1, *pw2, *pwl;
    cudaGetSymbolAddress(&pfb, g_fb);
    cudaGetSymbolAddress(&pxb, g_xb);
    cudaGetSymbolAddress(&ph1, g_h1b);
    cudaGetSymbolAddress(&ph2, g_h2b);
    cudaGetSymbolAddress(&pw1, g_w1b);
    cudaGetSymbolAddress(&pw2, g_w2b);
    cudaGetSymbolAddress(&pwl, g_wlb);

    const int SMEM_GEMM  = (128 + 64) * GSTR * 4;   //  52224 B
    const int SMEM_FINAL = (64 + 128) * FSTR * 4;   // 101376 B
    cudaFuncSetAttribute(k_gemm_relu, cudaFuncAttributeMaxDynamicSharedMemorySize, SMEM_GEMM);
    cudaFuncSetAttribute(k_final,     cudaFuncAttributeMaxDynamicSharedMemorySize, SMEM_FINAL);

    // CSR build
    k_zero<<<(n + 255) / 256, 256>>>(n);
    k_hist<<<(E + 255) / 256, 256>>>(dst, E);
    k_scan<<<1, 1024>>>(n);
    k_fill<<<(E + 255) / 256, 256>>>(src, dst, E);

    // fp32 -> bf16: feat + weights (weights once, blocks no longer convert)
    k_cvt<<<512, 256>>>((const float4*)feat, (uint2*)pfb, n * DH / 4);
    k_cvt<<<16, 256>>>((const float4*)W1, (uint2*)pw1, DH * DH / 4);
    k_cvt<<<16, 256>>>((const float4*)W2, (uint2*)pw2, DH * DH / 4);
    k_cvt<<<16, 256>>>((const float4*)Wl, (uint2*)pwl, NC * 2 * DH / 4);

    // layer 1
    k_agg<<<(n + 15) / 16, 256>>>((const __nv_bfloat16*)pfb, (__nv_bfloat16*)pxb, n);
    k_gemm_relu<<<(n + 63) / 64, 256, SMEM_GEMM>>>((const __nv_bfloat16*)pxb,
                                                   (const __nv_bfloat16*)pw1, b1,
                                                   (__nv_bfloat16*)ph1, n);

    // layer 2
    k_agg<<<(n + 15) / 16, 256>>>((const __nv_bfloat16*)ph1, (__nv_bfloat16*)pxb, n);
    k_gemm_relu<<<(n + 63) / 64, 256, SMEM_GEMM>>>((const __nv_bfloat16*)pxb,
                                                   (const __nv_bfloat16*)pw2, b2,
                                                   (__nv_bfloat16*)ph2, n);

    // classifier + log_softmax
    k_final<<<(n + 127) / 128, 256, SMEM_FINAL>>>((const __nv_bfloat16*)ph1,
                                                  (const __nv_bfloat16*)ph2,
                                                  (const __nv_bfloat16*)pwl, bl, out, n);
}

// round 11
// speedup vs baseline: 3.0566x; 1.0136x over previous
#include <cuda_runtime.h>
#include <cuda_bf16.h>
#include <math.h>
#include <stdint.h>

#define NN 100000
#define NE 1600000
#define DH 128
#define NC 64

// ---------------- scratch ----------------
__device__ int   g_deg[NN];
__device__ int   g_rowptr[NN + 1];
__device__ float g_invdeg[NN];
__device__ int   g_adj[NE];
__device__ __nv_bfloat16 g_fb [(size_t)NN * DH];  // feat in bf16
__device__ __nv_bfloat16 g_xb [(size_t)NN * DH];  // aggregated (bf16)
__device__ __nv_bfloat16 g_h1b[(size_t)NN * DH];
__device__ __nv_bfloat16 g_h2b[(size_t)NN * DH];
__device__ __nv_bfloat16 g_w1b[DH * DH];
__device__ __nv_bfloat16 g_w2b[DH * DH];
__device__ __nv_bfloat16 g_wlb[NC * 2 * DH];

__device__ __forceinline__ uint32_t pack_bf2(float x, float y) {
    __nv_bfloat162 h = __floats2bfloat162_rn(x, y);
    return *reinterpret_cast<uint32_t*>(&h);
}
__device__ __forceinline__ float2 unpack_bf2(uint32_t u) {
    __nv_bfloat162 h = *reinterpret_cast<__nv_bfloat162*>(&u);
    return __bfloat1622float2(h);
}
__device__ __forceinline__ void acc8(float* a, uint4 v) {
    float2 p;
    p = unpack_bf2(v.x); a[0] += p.x; a[1] += p.y;
    p = unpack_bf2(v.y); a[2] += p.x; a[3] += p.y;
    p = unpack_bf2(v.z); a[4] += p.x; a[5] += p.y;
    p = unpack_bf2(v.w); a[6] += p.x; a[7] += p.y;
}

__device__ __forceinline__ void mma_bf16(float& d0, float& d1, float& d2, float& d3,
                                         uint32_t a0, uint32_t a1, uint32_t a2, uint32_t a3,
                                         uint32_t b0, uint32_t b1) {
    asm volatile(
        "mma.sync.aligned.m16n8k16.row.col.f32.bf16.bf16.f32 "
        "{%0,%1,%2,%3}, {%4,%5,%6,%7}, {%8,%9}, {%0,%1,%2,%3};\n"
        : "+f"(d0), "+f"(d1), "+f"(d2), "+f"(d3)
        : "r"(a0), "r"(a1), "r"(a2), "r"(a3), "r"(b0), "r"(b1));
}

// ---------------- CSR build ----------------
__global__ void k_zero(int n) {
    int i = blockIdx.x * blockDim.x + threadIdx.x;
    if (i < n) g_deg[i] = 0;
}

__global__ void k_hist(const int* __restrict__ dst, int E) {
    int i = blockIdx.x * blockDim.x + threadIdx.x;
    if (i < E) atomicAdd(&g_deg[dst[i]], 1);
}

__global__ void k_scan(int n) {
    __shared__ int sums[1024];
    int tid = threadIdx.x;
    int per = (n + 1023) / 1024;
    int b = tid * per;
    int e = min(b + per, n);
    int s = 0;
    for (int i = b; i < e; i++) s += g_deg[i];
    sums[tid] = s;
    __syncthreads();
    for (int off = 1; off < 1024; off <<= 1) {
        int v = (tid >= off) ? sums[tid - off] : 0;
        __syncthreads();
        sums[tid] += v;
        __syncthreads();
    }
    int run = sums[tid] - s;
    for (int i = b; i < e; i++) {
        g_rowptr[i] = run;
        int d = g_deg[i];
        g_invdeg[i] = 1.0f / fmaxf((float)d, 1.0f);
        run += d;
    }
    if (tid == 1023) g_rowptr[n] = sums[1023];
}

// Fill bumps rowptr in place: after completion rowptr[d] = start(d+1)
// (exclusive-scan property), so agg uses s = rowptr[node-1], e = rowptr[node].
__global__ void k_fill(const int* __restrict__ src, const int* __restrict__ dst, int E) {
    int i = blockIdx.x * blockDim.x + threadIdx.x;
    if (i < E) {
        int p = atomicAdd(&g_rowptr[dst[i]], 1);
        g_adj[p] = src[i];
    }
}

// ---------------- fp32 -> bf16 convert (feat + all weights, one kernel) ----------------
__global__ void k_cvt_all(const float4* __restrict__ feat, const float4* __restrict__ w1,
                          const float4* __restrict__ w2, const float4* __restrict__ wl,
                          uint2* __restrict__ ofeat, uint2* __restrict__ ow1,
                          uint2* __restrict__ ow2, uint2* __restrict__ owl,
                          int nf, int nw, int nl) {
    int stride = gridDim.x * blockDim.x;
    int t0 = blockIdx.x * blockDim.x + threadIdx.x;
    for (int i = t0; i < nf; i += stride) {
        float4 v = feat[i];
        uint2 o; o.x = pack_bf2(v.x, v.y); o.y = pack_bf2(v.z, v.w);
        ofeat[i] = o;
    }
    for (int i = t0; i < nw; i += stride) {
        float4 v = w1[i];
        uint2 o; o.x = pack_bf2(v.x, v.y); o.y = pack_bf2(v.z, v.w);
        ow1[i] = o;
        v = w2[i];
        o.x = pack_bf2(v.x, v.y); o.y = pack_bf2(v.z, v.w);
        ow2[i] = o;
    }
    for (int i = t0; i < nl; i += stride) {
        float4 v = wl[i];
        uint2 o; o.x = pack_bf2(v.x, v.y); o.y = pack_bf2(v.z, v.w);
        owl[i] = o;
    }
}

// ---------------- mean aggregation: 2 nodes/warp, 16 lanes/node, unroll-8 ----------
__global__ void k_agg(const __nv_bfloat16* __restrict__ feat,
                      __nv_bfloat16* __restrict__ out, int n) {
    int warp = blockIdx.x * (blockDim.x >> 5) + (threadIdx.x >> 5);
    int lane = threadIdx.x & 31;
    int node = warp * 2 + (lane >> 4);
    if (node >= n) return;
    int hl = lane & 15;
    int e = g_rowptr[node];
    int s = (node > 0) ? g_rowptr[node - 1] : 0;
    const uint4* f4 = (const uint4*)feat;
    float acc[8];
#pragma unroll
    for (int k = 0; k < 8; k++) acc[k] = 0.f;
    int i = s;
    for (; i + 8 <= e; i += 8) {
        int j0 = g_adj[i],     j1 = g_adj[i + 1], j2 = g_adj[i + 2], j3 = g_adj[i + 3];
        int j4 = g_adj[i + 4], j5 = g_adj[i + 5], j6 = g_adj[i + 6], j7 = g_adj[i + 7];
        uint4 v0 = f4[(size_t)j0 * 16 + hl];
        uint4 v1 = f4[(size_t)j1 * 16 + hl];
        uint4 v2 = f4[(size_t)j2 * 16 + hl];
        uint4 v3 = f4[(size_t)j3 * 16 + hl];
        uint4 v4 = f4[(size_t)j4 * 16 + hl];
        uint4 v5 = f4[(size_t)j5 * 16 + hl];
        uint4 v6 = f4[(size_t)j6 * 16 + hl];
        uint4 v7 = f4[(size_t)j7 * 16 + hl];
        acc8(acc, v0); acc8(acc, v1); acc8(acc, v2); acc8(acc, v3);
        acc8(acc, v4); acc8(acc, v5); acc8(acc, v6); acc8(acc, v7);
    }
    for (; i + 4 <= e; i += 4) {
        int j0 = g_adj[i], j1 = g_adj[i + 1], j2 = g_adj[i + 2], j3 = g_adj[i + 3];
        uint4 v0 = f4[(size_t)j0 * 16 + hl];
        uint4 v1 = f4[(size_t)j1 * 16 + hl];
        uint4 v2 = f4[(size_t)j2 * 16 + hl];
        uint4 v3 = f4[(size_t)j3 * 16 + hl];
        acc8(acc, v0); acc8(acc, v1); acc8(acc, v2); acc8(acc, v3);
    }
    for (; i < e; i++) {
        uint4 v = f4[(size_t)g_adj[i] * 16 + hl];
        acc8(acc, v);
    }
    float sc = g_invdeg[node];
    uint4 o;
    o.x = pack_bf2(acc[0] * sc, acc[1] * sc);
    o.y = pack_bf2(acc[2] * sc, acc[3] * sc);
    o.z = pack_bf2(acc[4] * sc, acc[5] * sc);
    o.w = pack_bf2(acc[6] * sc, acc[7] * sc);
    ((uint4*)out)[(size_t)node * 16 + hl] = o;
}

// ---------------- bf16 GEMM: out = relu(A[M,128] @ W[128,128]^T + b) ----------------
#define GSTR 68
__global__ __launch_bounds__(256) void k_gemm_relu(
    const __nv_bfloat16* __restrict__ A, const __nv_bfloat16* __restrict__ Wb,
    const float* __restrict__ bias, __nv_bfloat16* __restrict__ out, int M) {
    extern __shared__ uint32_t smu[];
    uint32_t* Bs = smu;               // 128 x 68 u32
    uint32_t* As = smu + 128 * GSTR;  // 64 x 68
    int tid = threadIdx.x;

    for (int idx = tid; idx < 128 * 16; idx += 256) {
        int nrow = idx >> 4, c = idx & 15;
        uint4 v = ((const uint4*)Wb)[idx];
        *(uint4*)(Bs + nrow * GSTR + c * 4) = v;
    }
    int row0 = blockIdx.x * 64;
    for (int idx = tid; idx < 64 * 16; idx += 256) {
        int r = idx >> 4, c = idx & 15;
        int row = row0 + r;
        uint4 v = make_uint4(0u, 0u, 0u, 0u);
        if (row < M) v = ((const uint4*)A)[(size_t)row * 16 + c];
        *(uint4*)(As + r * GSTR + c * 4) = v;
    }
    __syncthreads();

    int lane = tid & 31, w = tid >> 5;
    int wm = w & 3, wn = w >> 2;
    int g = lane >> 2, tg = lane & 3;
    int arow0 = (wm * 16 + g) * GSTR;
    int arow1 = (wm * 16 + g + 8) * GSTR;

    float d[8][4];
#pragma unroll
    for (int nt = 0; nt < 8; nt++)
#pragma unroll
        for (int c = 0; c < 4; c++) d[nt][c] = 0.f;

#pragma unroll
    for (int kt = 0; kt < 8; kt++) {
        int k0 = kt * 8;
        uint32_t a0 = As[arow0 + k0 + tg];
        uint32_t a1 = As[arow1 + k0 + tg];
        uint32_t a2 = As[arow0 + k0 + tg + 4];
        uint32_t a3 = As[arow1 + k0 + tg + 4];
#pragma unroll
        for (int nt = 0; nt < 8; nt++) {
            int nb = (wn * 64 + nt * 8 + g) * GSTR + k0 + tg;
            uint32_t b0 = Bs[nb];
            uint32_t b1 = Bs[nb + 4];
            mma_bf16(d[nt][0], d[nt][1], d[nt][2], d[nt][3], a0, a1, a2, a3, b0, b1);
        }
    }

    int r0 = row0 + wm * 16 + g;
    int r1 = r0 + 8;
#pragma unroll
    for (int nt = 0; nt < 8; nt++) {
        int c = wn * 64 + nt * 8 + tg * 2;
        float bb0 = bias[c], bb1 = bias[c + 1];
        if (r0 < M)
            *(uint32_t*)(out + (size_t)r0 * 128 + c) =
                pack_bf2(fmaxf(d[nt][0] + bb0, 0.f), fmaxf(d[nt][1] + bb1, 0.f));
        if (r1 < M)
            *(uint32_t*)(out + (size_t)r1 * 128 + c) =
                pack_bf2(fmaxf(d[nt][2] + bb0, 0.f), fmaxf(d[nt][3] + bb1, 0.f));
    }
}

// ---------------- bf16 final: log_softmax([h1|h2] @ Wl^T + bl) ----------------
#define FSTR 132
__global__ __launch_bounds__(256) void k_final(
    const __nv_bfloat16* __restrict__ h1, const __nv_bfloat16* __restrict__ h2,
    const __nv_bfloat16* __restrict__ Wb, const float* __restrict__ bias,
    float* __restrict__ out, int M) {
    extern __shared__ uint32_t smu[];
    uint32_t* Bs = smu;              // 64 x 132 u32
    uint32_t* As = smu + 64 * FSTR;  // 128 x 132
    int tid = threadIdx.x;

    for (int idx = tid; idx < 64 * 32; idx += 256) {
        int nrow = idx >> 5, c = idx & 31;
        uint4 v = ((const uint4*)Wb)[idx];
        *(uint4*)(Bs + nrow * FSTR + c * 4) = v;
    }
    int row0 = blockIdx.x * 128;
    for (int idx = tid; idx < 128 * 32; idx += 256) {
        int r = idx >> 5, c = idx & 31;
        int row = row0 + r;
        uint4 v = make_uint4(0u, 0u, 0u, 0u);
        if (row < M) {
            if (c < 16) v = ((const uint4*)h1)[(size_t)row * 16 + c];
            else        v = ((const uint4*)h2)[(size_t)row * 16 + (c - 16)];
        }
        *(uint4*)(As + r * FSTR + c * 4) = v;
    }
    __syncthreads();

    int lane = tid & 31, w = tid >> 5;
    int g = lane >> 2, tg = lane & 3;
    int arow0 = (w * 16 + g) * FSTR;
    int arow1 = (w * 16 + g + 8) * FSTR;

    float d[8][4];
#pragma unroll
    for (int nt = 0; nt < 8; nt++)
#pragma unroll
        for (int c = 0; c < 4; c++) d[nt][c] = 0.f;

#pragma unroll
    for (int kt = 0; kt < 16; kt++) {
        int k0 = kt * 8;
        uint32_t a0 = As[arow0 + k0 + tg];
        uint32_t a1 = As[arow1 + k0 + tg];
        uint32_t a2 = As[arow0 + k0 + tg + 4];
        uint32_t a3 = As[arow1 + k0 + tg + 4];
#pragma unroll
        for (int nt = 0; nt < 8; nt++) {
            int nb = (nt * 8 + g) * FSTR + k0 + tg;
            uint32_t b0 = Bs[nb];
            uint32_t b1 = Bs[nb + 4];
            mma_bf16(d[nt][0], d[nt][1], d[nt][2], d[nt][3], a0, a1, a2, a3, b0, b1);
        }
    }

    float x0[16], x1[16];
#pragma unroll
    for (int nt = 0; nt < 8; nt++) {
        int c = nt * 8 + tg * 2;
        float bb0 = bias[c], bb1 = bias[c + 1];
        x0[2 * nt]     = d[nt][0] + bb0;
        x0[2 * nt + 1] = d[nt][1] + bb1;
        x1[2 * nt]     = d[nt][2] + bb0;
        x1[2 * nt + 1] = d[nt][3] + bb1;
    }

    float m0 = -1e30f, m1 = -1e30f;
#pragma unroll
    for (int i = 0; i < 16; i++) { m0 = fmaxf(m0, x0[i]); m1 = fmaxf(m1, x1[i]); }
    m0 = fmaxf(m0, __shfl_xor_sync(0xffffffffu, m0, 1));
    m0 = fmaxf(m0, __shfl_xor_sync(0xffffffffu, m0, 2));
    m1 = fmaxf(m1, __shfl_xor_sync(0xffffffffu, m1, 1));
    m1 = fmaxf(m1, __shfl_xor_sync(0xffffffffu, m1, 2));
    float s0 = 0.f, s1 = 0.f;
#pragma unroll
    for (int i = 0; i < 16; i++) { s0 += expf(x0[i] - m0); s1 += expf(x1[i] - m1); }
    s0 += __shfl_xor_sync(0xffffffffu, s0, 1);
    s0 += __shfl_xor_sync(0xffffffffu, s0, 2);
    s1 += __shfl_xor_sync(0xffffffffu, s1, 1);
    s1 += __shfl_xor_sync(0xffffffffu, s1, 2);
    float ls0 = m0 + logf(s0);
    float ls1 = m1 + logf(s1);

    int r0 = row0 + w * 16 + g;
    int r1 = r0 + 8;
#pragma unroll
    for (int nt = 0; nt < 8; nt++) {
        int c = nt * 8 + tg * 2;
        if (r0 < M) {
            float2 o; o.x = x0[2 * nt] - ls0; o.y = x0[2 * nt + 1] - ls0;
            *(float2*)(out + (size_t)r0 * 64 + c) = o;
        }
        if (r1 < M) {
            float2 o; o.x = x1[2 * nt] - ls1; o.y = x1[2 * nt + 1] - ls1;
            *(float2*)(out + (size_t)r1 * 64 + c) = o;
        }
    }
}

// ---------------- launch ----------------
extern "C" void kernel_launch(void* const* d_in, const int* in_sizes, int n_in,
                              void* d_out, int out_size) {
    const float* feat = (const float*)d_in[0];
    const int*   src  = (const int*)d_in[1];
    const int*   dst  = (const int*)d_in[2];
    const float* W1   = (const float*)d_in[3];
    const float* b1   = (const float*)d_in[4];
    const float* W2   = (const float*)d_in[5];
    const float* b2   = (const float*)d_in[6];
    const float* Wl   = (const float*)d_in[7];
    const float* bl   = (const float*)d_in[8];
    float* out = (float*)d_out;

    int n = in_sizes[0] / DH;
    int E = in_sizes[1];

    void *pfb, *pxb, *ph1, *ph2, *pw1, *pw2, *pwl;
    cudaGetSymbolAddress(&pfb, g_fb);
    cudaGetSymbolAddress(&pxb, g_xb);
    cudaGetSymbolAddress(&ph1, g_h1b);
    cudaGetSymbolAddress(&ph2, g_h2b);
    cudaGetSymbolAddress(&pw1, g_w1b);
    cudaGetSymbolAddress(&pw2, g_w2b);
    cudaGetSymbolAddress(&pwl, g_wlb);

    // one-time host-side stream/event setup (first call = correctness run,
    // happens before graph capture; no device memory involved)
    static cudaStream_t s2 = nullptr;
    static cudaEvent_t ev_fork = nullptr, ev_join = nullptr;
    if (!s2) {
        cudaStreamCreateWithFlags(&s2, cudaStreamNonBlocking);
        cudaEventCreateWithFlags(&ev_fork, cudaEventDisableTiming);
        cudaEventCreateWithFlags(&ev_join, cudaEventDisableTiming);
    }

    const int SMEM_GEMM  = (128 + 64) * GSTR * 4;   //  52224 B
    const int SMEM_FINAL = (64 + 128) * FSTR * 4;   // 101376 B
    cudaFuncSetAttribute(k_gemm_relu, cudaFuncAttributeMaxDynamicSharedMemorySize, SMEM_GEMM);
    cudaFuncSetAttribute(k_final,     cudaFuncAttributeMaxDynamicSharedMemorySize, SMEM_FINAL);

    // ---- fork: bf16 conversions run on s2, parallel to CSR build ----
    k_zero<<<(n + 255) / 256, 256>>>(n);
    cudaEventRecord(ev_fork, 0);
    cudaStreamWaitEvent(s2, ev_fork, 0);
    k_cvt_all<<<256, 256, 0, s2>>>((const float4*)feat, (const float4*)W1,
                                   (const float4*)W2, (const float4*)Wl,
                                   (uint2*)pfb, (uint2*)pw1, (uint2*)pw2, (uint2*)pwl,
                                   n * DH / 4, DH * DH / 4, NC * 2 * DH / 4);
    cudaEventRecord(ev_join, s2);

    // ---- CSR build on main stream ----
    k_hist<<<(E + 255) / 256, 256>>>(dst, E);
    k_scan<<<1, 1024>>>(n);
    k_fill<<<(E + 255) / 256, 256>>>(src, dst, E);

    // ---- join before aggregation ----
    cudaStreamWaitEvent(0, ev_join, 0);

    // layer 1
    k_agg<<<(n + 15) / 16, 256>>>((const __nv_bfloat16*)pfb, (__nv_bfloat16*)pxb, n);
    k_gemm_relu<<<(n + 63) / 64, 256, SMEM_GEMM>>>((const __nv_bfloat16*)pxb,
                                                   (const __nv_bfloat16*)pw1, b1,
                                                   (__nv_bfloat16*)ph1, n);

    // layer 2
    k_agg<<<(n + 15) / 16, 256>>>((const __nv_bfloat16*)ph1, (__nv_bfloat16*)pxb, n);
    k_gemm_relu<<<(n + 63) / 64, 256, SMEM_GEMM>>>((const __nv_bfloat16*)pxb,
                                                   (const __nv_bfloat16*)pw2, b2,
                                                   (__nv_bfloat16*)ph2, n);

    // classifier + log_softmax
    k_final<<<(n + 127) / 128, 256, SMEM_FINAL>>>((const __nv_bfloat16*)ph1,
                                                  (const __nv_bfloat16*)ph2,
                                                  (const __nv_bfloat16*)pwl, bl, out, n);
}

// round 12
// speedup vs baseline: 5.1105x; 1.6719x over previous
#include <cuda_runtime.h>
#include <cuda_bf16.h>
#include <math.h>
#include <stdint.h>

#define NN 100000
#define NE 1600000
#define DH 128
#define NC 64
#define SCAN_BS 1024   // elements per scan block

// ---------------- scratch ----------------
__device__ int   g_deg[NN];
__device__ int   g_rowptr[NN + 1];
__device__ int   g_bsum[256];
__device__ float g_invdeg[NN];
__device__ int   g_adj[NE];
__device__ __nv_bfloat16 g_fb [(size_t)NN * DH];  // feat in bf16
__device__ __nv_bfloat16 g_xb [(size_t)NN * DH];  // aggregated (bf16)
__device__ __nv_bfloat16 g_h1b[(size_t)NN * DH];
__device__ __nv_bfloat16 g_h2b[(size_t)NN * DH];
__device__ __nv_bfloat16 g_w1b[DH * DH];
__device__ __nv_bfloat16 g_w2b[DH * DH];
__device__ __nv_bfloat16 g_wlb[NC * 2 * DH];

__device__ __forceinline__ uint32_t pack_bf2(float x, float y) {
    __nv_bfloat162 h = __floats2bfloat162_rn(x, y);
    return *reinterpret_cast<uint32_t*>(&h);
}
__device__ __forceinline__ float2 unpack_bf2(uint32_t u) {
    __nv_bfloat162 h = *reinterpret_cast<__nv_bfloat162*>(&u);
    return __bfloat1622float2(h);
}
__device__ __forceinline__ void acc8(float* a, uint4 v) {
    float2 p;
    p = unpack_bf2(v.x); a[0] += p.x; a[1] += p.y;
    p = unpack_bf2(v.y); a[2] += p.x; a[3] += p.y;
    p = unpack_bf2(v.z); a[4] += p.x; a[5] += p.y;
    p = unpack_bf2(v.w); a[6] += p.x; a[7] += p.y;
}

__device__ __forceinline__ void mma_bf16(float& d0, float& d1, float& d2, float& d3,
                                         uint32_t a0, uint32_t a1, uint32_t a2, uint32_t a3,
                                         uint32_t b0, uint32_t b1) {
    asm volatile(
        "mma.sync.aligned.m16n8k16.row.col.f32.bf16.bf16.f32 "
        "{%0,%1,%2,%3}, {%4,%5,%6,%7}, {%8,%9}, {%0,%1,%2,%3};\n"
        : "+f"(d0), "+f"(d1), "+f"(d2), "+f"(d3)
        : "r"(a0), "r"(a1), "r"(a2), "r"(a3), "r"(b0), "r"(b1));
}

// ---------------- CSR build ----------------
__global__ void k_zero(int n) {
    int i = blockIdx.x * blockDim.x + threadIdx.x;
    if (i < n) g_deg[i] = 0;
}

__global__ void k_hist(const int* __restrict__ dst, int E) {
    int i = blockIdx.x * blockDim.x + threadIdx.x;
    if (i < E) atomicAdd(&g_deg[dst[i]], 1);
}

// Phase 1: block-local exclusive scan (1024 elems/block, 256 thr x 4),
// writes local prefixes to rowptr, invdeg, and per-block totals.
__global__ void k_scan1(int n) {
    int tid = threadIdx.x;
    int base = blockIdx.x * SCAN_BS + tid * 4;
    int d[4];
#pragma unroll
    for (int k = 0; k < 4; k++) d[k] = (base + k < n) ? g_deg[base + k] : 0;
    int tsum = d[0] + d[1] + d[2] + d[3];

    int lane = tid & 31, w = tid >> 5;
    int x = tsum;
#pragma unroll
    for (int off = 1; off < 32; off <<= 1) {
        int y = __shfl_up_sync(0xffffffffu, x, off);
        if (lane >= off) x += y;
    }
    __shared__ int wsum[8];
    if (lane == 31) wsum[w] = x;
    __syncthreads();
    if (tid < 8) {
        int a = wsum[tid];
#pragma unroll
        for (int off = 1; off < 8; off <<= 1) {
            int y = __shfl_up_sync(0xffu, a, off);
            if (tid >= off) a += y;
        }
        wsum[tid] = a;
    }
    __syncthreads();
    int run = ((w > 0) ? wsum[w - 1] : 0) + (x - tsum);  // thread-exclusive prefix
#pragma unroll
    for (int k = 0; k < 4; k++) {
        if (base + k < n) {
            g_rowptr[base + k] = run;
            g_invdeg[base + k] = 1.0f / fmaxf((float)d[k], 1.0f);
            run += d[k];
        }
    }
    if (tid == 0) g_bsum[blockIdx.x] = wsum[7];
}

// Phase 2: exclusive scan of block totals (nb <= 128).
__global__ void k_scan2(int nb) {
    int tid = threadIdx.x;  // 128 threads
    int v = (tid < nb) ? g_bsum[tid] : 0;
    int lane = tid & 31, w = tid >> 5;
    int x = v;
#pragma unroll
    for (int off = 1; off < 32; off <<= 1) {
        int y = __shfl_up_sync(0xffffffffu, x, off);
        if (lane >= off) x += y;
    }
    __shared__ int ws[4];
    if (lane == 31) ws[w] = x;
    __syncthreads();
    if (tid < 4) {
        int a = ws[tid];
#pragma unroll
        for (int off = 1; off < 4; off <<= 1) {
            int y = __shfl_up_sync(0xfu, a, off);
            if (tid >= off) a += y;
        }
        ws[tid] = a;
    }
    __syncthreads();
    int excl = (x - v) + ((w > 0) ? ws[w - 1] : 0);
    if (tid < nb) g_bsum[tid] = excl;
}

// Phase 3: add block offsets to rowptr.
__global__ void k_scan3(int n) {
    int base = blockIdx.x * SCAN_BS + threadIdx.x * 4;
    int off = g_bsum[blockIdx.x];
    if (base + 3 < n) {
        int4 v = *(int4*)&g_rowptr[base];
        v.x += off; v.y += off; v.z += off; v.w += off;
        *(int4*)&g_rowptr[base] = v;
    } else {
        for (int k = 0; k < 4; k++)
            if (base + k < n) g_rowptr[base + k] += off;
    }
}

// Fill bumps rowptr in place: after completion rowptr[d] = start(d+1),
// so agg uses s = rowptr[node-1], e = rowptr[node].
__global__ void k_fill(const int* __restrict__ src, const int* __restrict__ dst, int E) {
    int i = blockIdx.x * blockDim.x + threadIdx.x;
    if (i < E) {
        int p = atomicAdd(&g_rowptr[dst[i]], 1);
        g_adj[p] = src[i];
    }
}

// ---------------- fp32 -> bf16 convert (feat + all weights, one kernel) ----------------
__global__ void k_cvt_all(const float4* __restrict__ feat, const float4* __restrict__ w1,
                          const float4* __restrict__ w2, const float4* __restrict__ wl,
                          uint2* __restrict__ ofeat, uint2* __restrict__ ow1,
                          uint2* __restrict__ ow2, uint2* __restrict__ owl,
                          int nf, int nw, int nl) {
    int stride = gridDim.x * blockDim.x;
    int t0 = blockIdx.x * blockDim.x + threadIdx.x;
    for (int i = t0; i < nf; i += stride) {
        float4 v = feat[i];
        uint2 o; o.x = pack_bf2(v.x, v.y); o.y = pack_bf2(v.z, v.w);
        ofeat[i] = o;
    }
    for (int i = t0; i < nw; i += stride) {
        float4 v = w1[i];
        uint2 o; o.x = pack_bf2(v.x, v.y); o.y = pack_bf2(v.z, v.w);
        ow1[i] = o;
        v = w2[i];
        o.x = pack_bf2(v.x, v.y); o.y = pack_bf2(v.z, v.w);
        ow2[i] = o;
    }
    for (int i = t0; i < nl; i += stride) {
        float4 v = wl[i];
        uint2 o; o.x = pack_bf2(v.x, v.y); o.y = pack_bf2(v.z, v.w);
        owl[i] = o;
    }
}

// ---------------- mean aggregation: 2 nodes/warp, 16 lanes/node, unroll-8 ----------
__global__ void k_agg(const __nv_bfloat16* __restrict__ feat,
                      __nv_bfloat16* __restrict__ out, int n) {
    int warp = blockIdx.x * (blockDim.x >> 5) + (threadIdx.x >> 5);
    int lane = threadIdx.x & 31;
    int node = warp * 2 + (lane >> 4);
    if (node >= n) return;
    int hl = lane & 15;
    int e = g_rowptr[node];
    int s = (node > 0) ? g_rowptr[node - 1] : 0;
    const uint4* f4 = (const uint4*)feat;
    float acc[8];
#pragma unroll
    for (int k = 0; k < 8; k++) acc[k] = 0.f;
    int i = s;
    for (; i + 8 <= e; i += 8) {
        int j0 = g_adj[i],     j1 = g_adj[i + 1], j2 = g_adj[i + 2], j3 = g_adj[i + 3];
        int j4 = g_adj[i + 4], j5 = g_adj[i + 5], j6 = g_adj[i + 6], j7 = g_adj[i + 7];
        uint4 v0 = f4[(size_t)j0 * 16 + hl];
        uint4 v1 = f4[(size_t)j1 * 16 + hl];
        uint4 v2 = f4[(size_t)j2 * 16 + hl];
        uint4 v3 = f4[(size_t)j3 * 16 + hl];
        uint4 v4 = f4[(size_t)j4 * 16 + hl];
        uint4 v5 = f4[(size_t)j5 * 16 + hl];
        uint4 v6 = f4[(size_t)j6 * 16 + hl];
        uint4 v7 = f4[(size_t)j7 * 16 + hl];
        acc8(acc, v0); acc8(acc, v1); acc8(acc, v2); acc8(acc, v3);
        acc8(acc, v4); acc8(acc, v5); acc8(acc, v6); acc8(acc, v7);
    }
    for (; i + 4 <= e; i += 4) {
        int j0 = g_adj[i], j1 = g_adj[i + 1], j2 = g_adj[i + 2], j3 = g_adj[i + 3];
        uint4 v0 = f4[(size_t)j0 * 16 + hl];
        uint4 v1 = f4[(size_t)j1 * 16 + hl];
        uint4 v2 = f4[(size_t)j2 * 16 + hl];
        uint4 v3 = f4[(size_t)j3 * 16 + hl];
        acc8(acc, v0); acc8(acc, v1); acc8(acc, v2); acc8(acc, v3);
    }
    for (; i < e; i++) {
        uint4 v = f4[(size_t)g_adj[i] * 16 + hl];
        acc8(acc, v);
    }
    float sc = g_invdeg[node];
    uint4 o;
    o.x = pack_bf2(acc[0] * sc, acc[1] * sc);
    o.y = pack_bf2(acc[2] * sc, acc[3] * sc);
    o.z = pack_bf2(acc[4] * sc, acc[5] * sc);
    o.w = pack_bf2(acc[6] * sc, acc[7] * sc);
    ((uint4*)out)[(size_t)node * 16 + hl] = o;
}

// ---------------- bf16 GEMM: out = relu(A[M,128] @ W[128,128]^T + b) ----------------
#define GSTR 68
__global__ __launch_bounds__(256) void k_gemm_relu(
    const __nv_bfloat16* __restrict__ A, const __nv_bfloat16* __restrict__ Wb,
    const float* __restrict__ bias, __nv_bfloat16* __restrict__ out, int M) {
    extern __shared__ uint32_t smu[];
    uint32_t* Bs = smu;               // 128 x 68 u32
    uint32_t* As = smu + 128 * GSTR;  // 64 x 68
    int tid = threadIdx.x;

    for (int idx = tid; idx < 128 * 16; idx += 256) {
        int nrow = idx >> 4, c = idx & 15;
        uint4 v = ((const uint4*)Wb)[idx];
        *(uint4*)(Bs + nrow * GSTR + c * 4) = v;
    }
    int row0 = blockIdx.x * 64;
    for (int idx = tid; idx < 64 * 16; idx += 256) {
        int r = idx >> 4, c = idx & 15;
        int row = row0 + r;
        uint4 v = make_uint4(0u, 0u, 0u, 0u);
        if (row < M) v = ((const uint4*)A)[(size_t)row * 16 + c];
        *(uint4*)(As + r * GSTR + c * 4) = v;
    }
    __syncthreads();

    int lane = tid & 31, w = tid >> 5;
    int wm = w & 3, wn = w >> 2;
    int g = lane >> 2, tg = lane & 3;
    int arow0 = (wm * 16 + g) * GSTR;
    int arow1 = (wm * 16 + g + 8) * GSTR;

    float d[8][4];
#pragma unroll
    for (int nt = 0; nt < 8; nt++)
#pragma unroll
        for (int c = 0; c < 4; c++) d[nt][c] = 0.f;

#pragma unroll
    for (int kt = 0; kt < 8; kt++) {
        int k0 = kt * 8;
        uint32_t a0 = As[arow0 + k0 + tg];
        uint32_t a1 = As[arow1 + k0 + tg];
        uint32_t a2 = As[arow0 + k0 + tg + 4];
        uint32_t a3 = As[arow1 + k0 + tg + 4];
#pragma unroll
        for (int nt = 0; nt < 8; nt++) {
            int nb = (wn * 64 + nt * 8 + g) * GSTR + k0 + tg;
            uint32_t b0 = Bs[nb];
            uint32_t b1 = Bs[nb + 4];
            mma_bf16(d[nt][0], d[nt][1], d[nt][2], d[nt][3], a0, a1, a2, a3, b0, b1);
        }
    }

    int r0 = row0 + wm * 16 + g;
    int r1 = r0 + 8;
#pragma unroll
    for (int nt = 0; nt < 8; nt++) {
        int c = wn * 64 + nt * 8 + tg * 2;
        float bb0 = bias[c], bb1 = bias[c + 1];
        if (r0 < M)
            *(uint32_t*)(out + (size_t)r0 * 128 + c) =
                pack_bf2(fmaxf(d[nt][0] + bb0, 0.f), fmaxf(d[nt][1] + bb1, 0.f));
        if (r1 < M)
            *(uint32_t*)(out + (size_t)r1 * 128 + c) =
                pack_bf2(fmaxf(d[nt][2] + bb0, 0.f), fmaxf(d[nt][3] + bb1, 0.f));
    }
}

// ---------------- bf16 final: log_softmax([h1|h2] @ Wl^T + bl) ----------------
#define FSTR 132
__global__ __launch_bounds__(256) void k_final(
    const __nv_bfloat16* __restrict__ h1, const __nv_bfloat16* __restrict__ h2,
    const __nv_bfloat16* __restrict__ Wb, const float* __restrict__ bias,
    float* __restrict__ out, int M) {
    extern __shared__ uint32_t smu[];
    uint32_t* Bs = smu;              // 64 x 132 u32
    uint32_t* As = smu + 64 * FSTR;  // 128 x 132
    int tid = threadIdx.x;

    for (int idx = tid; idx < 64 * 32; idx += 256) {
        int nrow = idx >> 5, c = idx & 31;
        uint4 v = ((const uint4*)Wb)[idx];
        *(uint4*)(Bs + nrow * FSTR + c * 4) = v;
    }
    int row0 = blockIdx.x * 128;
    for (int idx = tid; idx < 128 * 32; idx += 256) {
        int r = idx >> 5, c = idx & 31;
        int row = row0 + r;
        uint4 v = make_uint4(0u, 0u, 0u, 0u);
        if (row < M) {
            if (c < 16) v = ((const uint4*)h1)[(size_t)row * 16 + c];
            else        v = ((const uint4*)h2)[(size_t)row * 16 + (c - 16)];
        }
        *(uint4*)(As + r * FSTR + c * 4) = v;
    }
    __syncthreads();

    int lane = tid & 31, w = tid >> 5;
    int g = lane >> 2, tg = lane & 3;
    int arow0 = (w * 16 + g) * FSTR;
    int arow1 = (w * 16 + g + 8) * FSTR;

    float d[8][4];
#pragma unroll
    for (int nt = 0; nt < 8; nt++)
#pragma unroll
        for (int c = 0; c < 4; c++) d[nt][c] = 0.f;

#pragma unroll
    for (int kt = 0; kt < 16; kt++) {
        int k0 = kt * 8;
        uint32_t a0 = As[arow0 + k0 + tg];
        uint32_t a1 = As[arow1 + k0 + tg];
        uint32_t a2 = As[arow0 + k0 + tg + 4];
        uint32_t a3 = As[arow1 + k0 + tg + 4];
#pragma unroll
        for (int nt = 0; nt < 8; nt++) {
            int nb = (nt * 8 + g) * FSTR + k0 + tg;
            uint32_t b0 = Bs[nb];
            uint32_t b1 = Bs[nb + 4];
            mma_bf16(d[nt][0], d[nt][1], d[nt][2], d[nt][3], a0, a1, a2, a3, b0, b1);
        }
    }

    float x0[16], x1[16];
#pragma unroll
    for (int nt = 0; nt < 8; nt++) {
        int c = nt * 8 + tg * 2;
        float bb0 = bias[c], bb1 = bias[c + 1];
        x0[2 * nt]     = d[nt][0] + bb0;
        x0[2 * nt + 1] = d[nt][1] + bb1;
        x1[2 * nt]     = d[nt][2] + bb0;
        x1[2 * nt + 1] = d[nt][3] + bb1;
    }

    float m0 = -1e30f, m1 = -1e30f;
#pragma unroll
    for (int i = 0; i < 16; i++) { m0 = fmaxf(m0, x0[i]); m1 = fmaxf(m1, x1[i]); }
    m0 = fmaxf(m0, __shfl_xor_sync(0xffffffffu, m0, 1));
    m0 = fmaxf(m0, __shfl_xor_sync(0xffffffffu, m0, 2));
    m1 = fmaxf(m1, __shfl_xor_sync(0xffffffffu, m1, 1));
    m1 = fmaxf(m1, __shfl_xor_sync(0xffffffffu, m1, 2));
    float s0 = 0.f, s1 = 0.f;
#pragma unroll
    for (int i = 0; i < 16; i++) { s0 += expf(x0[i] - m0); s1 += expf(x1[i] - m1); }
    s0 += __shfl_xor_sync(0xffffffffu, s0, 1);
    s0 += __shfl_xor_sync(0xffffffffu, s0, 2);
    s1 += __shfl_xor_sync(0xffffffffu, s1, 1);
    s1 += __shfl_xor_sync(0xffffffffu, s1, 2);
    float ls0 = m0 + logf(s0);
    float ls1 = m1 + logf(s1);

    int r0 = row0 + w * 16 + g;
    int r1 = r0 + 8;
#pragma unroll
    for (int nt = 0; nt < 8; nt++) {
        int c = nt * 8 + tg * 2;
        if (r0 < M) {
            float2 o; o.x = x0[2 * nt] - ls0; o.y = x0[2 * nt + 1] - ls0;
            *(float2*)(out + (size_t)r0 * 64 + c) = o;
        }
        if (r1 < M) {
            float2 o; o.x = x1[2 * nt] - ls1; o.y = x1[2 * nt + 1] - ls1;
            *(float2*)(out + (size_t)r1 * 64 + c) = o;
        }
    }
}

// ---------------- launch ----------------
extern "C" void kernel_launch(void* const* d_in, const int* in_sizes, int n_in,
                              void* d_out, int out_size) {
    const float* feat = (const float*)d_in[0];
    const int*   src  = (const int*)d_in[1];
    const int*   dst  = (const int*)d_in[2];
    const float* W1   = (const float*)d_in[3];
    const float* b1   = (const float*)d_in[4];
    const float* W2   = (const float*)d_in[5];
    const float* b2   = (const float*)d_in[6];
    const float* Wl   = (const float*)d_in[7];
    const float* bl   = (const float*)d_in[8];
    float* out = (float*)d_out;

    int n = in_sizes[0] / DH;
    int E = in_sizes[1];
    int nblk = (n + SCAN_BS - 1) / SCAN_BS;

    void *pfb, *pxb, *ph1, *ph2, *pw1, *pw2, *pwl;
    cudaGetSymbolAddress(&pfb, g_fb);
    cudaGetSymbolAddress(&pxb, g_xb);
    cudaGetSymbolAddress(&ph1, g_h1b);
    cudaGetSymbolAddress(&ph2, g_h2b);
    cudaGetSymbolAddress(&pw1, g_w1b);
    cudaGetSymbolAddress(&pw2, g_w2b);
    cudaGetSymbolAddress(&pwl, g_wlb);

    static cudaStream_t s2 = nullptr;
    static cudaEvent_t ev_fork = nullptr, ev_join = nullptr;
    if (!s2) {
        cudaStreamCreateWithFlags(&s2, cudaStreamNonBlocking);
        cudaEventCreateWithFlags(&ev_fork, cudaEventDisableTiming);
        cudaEventCreateWithFlags(&ev_join, cudaEventDisableTiming);
    }

    const int SMEM_GEMM  = (128 + 64) * GSTR * 4;   //  52224 B
    const int SMEM_FINAL = (64 + 128) * FSTR * 4;   // 101376 B
    cudaFuncSetAttribute(k_gemm_relu, cudaFuncAttributeMaxDynamicSharedMemorySize, SMEM_GEMM);
    cudaFuncSetAttribute(k_final,     cudaFuncAttributeMaxDynamicSharedMemorySize, SMEM_FINAL);

    // ---- fork: bf16 conversions run on s2, parallel to CSR build ----
    k_zero<<<(n + 255) / 256, 256>>>(n);
    cudaEventRecord(ev_fork, 0);
    cudaStreamWaitEvent(s2, ev_fork, 0);
    k_cvt_all<<<256, 256, 0, s2>>>((const float4*)feat, (const float4*)W1,
                                   (const float4*)W2, (const float4*)Wl,
                                   (uint2*)pfb, (uint2*)pw1, (uint2*)pw2, (uint2*)pwl,
                                   n * DH / 4, DH * DH / 4, NC * 2 * DH / 4);
    cudaEventRecord(ev_join, s2);

    // ---- CSR build on main stream (multi-block scan) ----
    k_hist<<<(E + 255) / 256, 256>>>(dst, E);
    k_scan1<<<nblk, 256>>>(n);
    k_scan2<<<1, 128>>>(nblk);
    k_scan3<<<nblk, 256>>>(n);
    k_fill<<<(E + 255) / 256, 256>>>(src, dst, E);

    // ---- join before aggregation ----
    cudaStreamWaitEvent(0, ev_join, 0);

    // layer 1
    k_agg<<<(n + 15) / 16, 256>>>((const __nv_bfloat16*)pfb, (__nv_bfloat16*)pxb, n);
    k_gemm_relu<<<(n + 63) / 64, 256, SMEM_GEMM>>>((const __nv_bfloat16*)pxb,
                                                   (const __nv_bfloat16*)pw1, b1,
                                                   (__nv_bfloat16*)ph1, n);

    // layer 2
    k_agg<<<(n + 15) / 16, 256>>>((const __nv_bfloat16*)ph1, (__nv_bfloat16*)pxb, n);
    k_gemm_relu<<<(n + 63) / 64, 256, SMEM_GEMM>>>((const __nv_bfloat16*)pxb,
                                                   (const __nv_bfloat16*)pw2, b2,
                                                   (__nv_bfloat16*)ph2, n);

    // classifier + log_softmax
    k_final<<<(n + 127) / 128, 256, SMEM_FINAL>>>((const __nv_bfloat16*)ph1,
                                                  (const __nv_bfloat16*)ph2,
                                                  (const __nv_bfloat16*)pwl, bl, out, n);
}